// round 14
// baseline (speedup 1.0000x reference)
#include <cuda_runtime.h>
#include <cstdint>

// ---------------- Problem constants ----------------
#define NA   20001
#define FD   133
#define KNB  6
#define HD   1100
#define FHD  700
#define NM   800
#define FFK  1400

// K paddings in PAIRS (bf16x2). Multiples of 16 pairs = 32 elems (one stage).
#define JP_FA   80      // si : T=5
#define JP_X    144     // vi : T=9
#define JP_H    560     // hs/hv : T=35
#define JP_OS   624     // os : T=39
#define JP_OV   1104    // ov : T=69
#define JP_FF   704     // ffn : T=44

// ---------------- Scratch (device globals) ----------------
__device__ __align__(16) uint2 g_fa_p  [(size_t)NA * JP_FA];
__device__ __align__(16) uint2 g_X_p   [(size_t)NA * 3 * JP_X];
__device__ __align__(16) uint2 g_sagg_p[(size_t)NA * JP_H];
__device__ __align__(16) uint2 g_vagg_p[(size_t)NA * 3 * JP_H];
__device__ __align__(16) uint2 g_osin_p[(size_t)NA * JP_OS];
__device__ __align__(16) uint2 g_ovin_p[(size_t)NA * 3 * JP_OV];
__device__ __align__(16) uint2 g_mol_p [(size_t)NM * JP_FF];

__device__ __align__(16) uint2 g_Wis_p [(size_t)JP_FA * HD];
__device__ __align__(16) uint2 g_Wiv_p [(size_t)JP_X  * HD];
__device__ __align__(16) uint2 g_Whs_p [(size_t)JP_H  * HD];
__device__ __align__(16) uint2 g_Whv_p [(size_t)JP_H  * HD];
__device__ __align__(16) uint2 g_Wos_p [(size_t)JP_OS * FHD];
__device__ __align__(16) uint2 g_Wov_p [(size_t)JP_OV * FHD];
__device__ __align__(16) uint2 g_Wff_p [(size_t)JP_FF * FHD];

__device__ __align__(16) float g_si [(size_t)NA * HD];
__device__ __align__(16) float g_s  [(size_t)NA * HD];
__device__ __align__(16) float g_vi [(size_t)NA * 3 * HD];
__device__ __align__(16) float g_v  [(size_t)NA * 3 * HD];
__device__ __align__(16) float g_osb[(size_t)NA * FHD];
__device__ __align__(16) float g_ovb[(size_t)NA * 3 * FHD];
__device__ __align__(16) float g_o  [(size_t)NA * FFK];
__device__ __align__(16) float g_h  [NM * FHD];
__device__ int g_molstart[NM + 1];

// ---------------- bf16 split-pack helper ----------------
__device__ __forceinline__ uint2 splitpack(float x0, float x1) {
    unsigned h;
    asm("cvt.rn.bf16x2.f32 %0, %1, %2;" : "=r"(h) : "f"(x1), "f"(x0));
    float h0 = __uint_as_float(h << 16);
    float h1 = __uint_as_float(h & 0xFFFF0000u);
    unsigned l;
    asm("cvt.rn.bf16x2.f32 %0, %1, %2;" : "=r"(l) : "f"(x1 - h1), "f"(x0 - h0));
    return make_uint2(h, l);
}

__device__ __forceinline__ uint4 splitpack4(float4 a) {
    uint2 r0 = splitpack(a.x, a.y);
    uint2 r1 = splitpack(a.z, a.w);
    return make_uint4(r0.x, r0.y, r1.x, r1.y);
}

__device__ __forceinline__ void cp16(void* dst_smem, const void* src, int bytes) {
    unsigned sa = (unsigned)__cvta_generic_to_shared(dst_smem);
    asm volatile("cp.async.ca.shared.global [%0], [%1], 16, %2;\n"
                 :: "r"(sa), "l"(src), "r"(bytes));
}

#define MMA_BF16(ACC, AF, BF)                                                   \
    asm volatile(                                                               \
        "mma.sync.aligned.m16n8k16.row.col.f32.bf16.bf16.f32 "                  \
        "{%0,%1,%2,%3}, {%4,%5,%6,%7}, {%8,%9}, {%0,%1,%2,%3};\n"               \
        : "+f"(ACC[0]), "+f"(ACC[1]), "+f"(ACC[2]), "+f"(ACC[3])                \
        : "r"(AF[0]), "r"(AF[1]), "r"(AF[2]), "r"(AF[3]),                       \
          "r"(BF[0]), "r"(BF[1]))

// ---------------- bf16x3 dual-problem GEMM, 256x128 tile ----------------
// 8 warps, each 64x64 (wm = (warp&3)*64, wn = (warp>>2)*64).
// BK=32/stage, double-buffered, one __syncthreads per stage.
#define BMROW 256
#define ASTP 18
#define BSTP 132
#define STG_A (BMROW * ASTP)          // uint2
#define STG_B (16 * BSTP)             // uint2
#define STG_U2 (STG_A + STG_B)        // 6720 uint2 = 53760 B
#define SMEM_GEMM (2 * STG_U2 * 8)    // 107520 B

template<bool RELU, bool HAS_ADD, bool HAS_BIAS, bool WRITE_RAW>
__global__ __launch_bounds__(256, 1)
void bgemm_kernel(const uint2* __restrict__ A0, const uint2* __restrict__ B0,
                  const float* __restrict__ Add0, const float* __restrict__ bias0,
                  float* __restrict__ C0, float* __restrict__ Craw0,
                  int M0, int T0, int ldp0,
                  const uint2* __restrict__ A1, const uint2* __restrict__ B1,
                  const float* __restrict__ Add1, const float* __restrict__ bias1,
                  float* __restrict__ C1, float* __restrict__ Craw1,
                  int M1, int T1, int ldp1,
                  int N, int tiles0)
{
    extern __shared__ __align__(16) uint2 smem_u2[];

    const bool p1 = (int)blockIdx.y >= tiles0;
    const uint2* __restrict__ A   = p1 ? A1   : A0;
    const uint2* __restrict__ B   = p1 ? B1   : B0;
    const float* __restrict__ Add = p1 ? Add1 : Add0;
    const float* __restrict__ bias= p1 ? bias1: bias0;
    float* __restrict__ C    = p1 ? C1    : C0;
    float* __restrict__ Craw = p1 ? Craw1 : Craw0;
    const int M   = p1 ? M1   : M0;
    const int T   = p1 ? T1   : T0;
    const int ldp = p1 ? ldp1 : ldp0;
    const int rowBase = (p1 ? ((int)blockIdx.y - tiles0) : (int)blockIdx.y) * BMROW;

    const int tid = threadIdx.x;
    const int colBase = blockIdx.x * 128;
    const int warpId = tid >> 5;
    const int lane = tid & 31;
    const int g  = lane >> 2;
    const int tg = lane & 3;
    const int wm = (warpId & 3) * 64;
    const int wn = (warpId >> 2) * 64;

    float acc[4][8][4];
    #pragma unroll
    for (int mi = 0; mi < 4; mi++)
        #pragma unroll
        for (int ni = 0; ni < 8; ni++)
            #pragma unroll
            for (int j = 0; j < 4; j++) acc[mi][ni][j] = 0.f;

    auto load_stage = [&](int t, int st) {
        uint2* As = smem_u2 + st * STG_U2;
        uint2* Bs = As + STG_A;
        #pragma unroll
        for (int i = 0; i < 8; i++) {        // A: 2048 chunks (16B = 2 pairs)
            int c = tid + i * 256;
            int m = c >> 3, q = c & 7;
            int gm = rowBase + m;
            bool ok = gm < M;
            const uint2* src = ok ? (A + (size_t)gm * ldp + t * 16 + q * 2) : A;
            cp16(&As[m * ASTP + q * 2], src, ok ? 16 : 0);
        }
        #pragma unroll
        for (int i = 0; i < 4; i++) {        // B: 1024 chunks (2 cols)
            int c = tid + i * 256;
            int j = c >> 6, q = c & 63;
            int gn = colBase + q * 2;
            bool ok = gn < N;
            const uint2* src = ok ? (B + (size_t)(t * 16 + j) * N + gn) : B;
            cp16(&Bs[j * BSTP + q * 2], src, ok ? 16 : 0);
        }
        asm volatile("cp.async.commit_group;\n");
    };

    load_stage(0, 0);

    for (int t = 0; t < T; t++) {
        const int st = t & 1;
        asm volatile("cp.async.wait_group 0;\n");
        __syncthreads();

        if (t + 1 < T) load_stage(t + 1, st ^ 1);

        const uint2* As = smem_u2 + st * STG_U2;
        const uint2* Bs = As + STG_A;

        #pragma unroll
        for (int ks = 0; ks < 2; ks++) {
            const int kb = ks * 8;
            unsigned ah[4][4], al[4][4], bh[8][2], bl[8][2];
            #pragma unroll
            for (int mi = 0; mi < 4; mi++) {
                int r = wm + mi * 16 + g;
                uint2 p0 = As[r * ASTP + kb + tg];
                uint2 q1 = As[(r + 8) * ASTP + kb + tg];
                uint2 p2 = As[r * ASTP + kb + 4 + tg];
                uint2 p3 = As[(r + 8) * ASTP + kb + 4 + tg];
                ah[mi][0] = p0.x; ah[mi][1] = q1.x; ah[mi][2] = p2.x; ah[mi][3] = p3.x;
                al[mi][0] = p0.y; al[mi][1] = q1.y; al[mi][2] = p2.y; al[mi][3] = p3.y;
            }
            #pragma unroll
            for (int ni = 0; ni < 8; ni++) {
                int n = wn + ni * 8 + g;
                uint2 q0 = Bs[(kb + tg) * BSTP + n];
                uint2 q1 = Bs[(kb + 4 + tg) * BSTP + n];
                bh[ni][0] = q0.x; bh[ni][1] = q1.x;
                bl[ni][0] = q0.y; bl[ni][1] = q1.y;
            }
            #pragma unroll
            for (int mi = 0; mi < 4; mi++)
                #pragma unroll
                for (int ni = 0; ni < 8; ni++) {
                    MMA_BF16(acc[mi][ni], ah[mi], bl[ni]);   // hi*lo
                    MMA_BF16(acc[mi][ni], al[mi], bh[ni]);   // lo*hi
                    MMA_BF16(acc[mi][ni], ah[mi], bh[ni]);   // hi*hi last
                }
        }
    }

    #pragma unroll
    for (int mi = 0; mi < 4; mi++) {
        int r0 = rowBase + wm + mi * 16 + g;
        #pragma unroll
        for (int ni = 0; ni < 8; ni++) {
            int cN = colBase + wn + ni * 8 + tg * 2;
            if (cN >= N) continue;
            #pragma unroll
            for (int half = 0; half < 2; half++) {
                int r = r0 + half * 8;
                if (r >= M) continue;
                size_t idx = (size_t)r * N + cN;
                float2 vv;
                vv.x = acc[mi][ni][half * 2 + 0];
                vv.y = acc[mi][ni][half * 2 + 1];
                if (HAS_ADD) {
                    float2 a = *(const float2*)(Add + idx);
                    vv.x += a.x; vv.y += a.y;
                }
                if (HAS_BIAS) {
                    float2 b = *(const float2*)(bias + cN);
                    vv.x += b.x; vv.y += b.y;
                }
                if (WRITE_RAW) *(float2*)(Craw + idx) = vv;
                if (RELU) { vv.x = fmaxf(vv.x, 0.f); vv.y = fmaxf(vv.y, 0.f); }
                *(float2*)(C + idx) = vv;
            }
        }
    }
}

// ---------------- weight split-pack (2-segment k remap), layout [j][n] ----------------
__global__ void packW_kernel(const float* __restrict__ W, int N, int Jtot,
                             int s0, int l0, int d0, int s1, int l1, int d1,
                             uint2* __restrict__ out)
{
    long tot = (long)Jtot * N;
    for (long idx = (long)blockIdx.x * blockDim.x + threadIdx.x; idx < tot;
         idx += (long)gridDim.x * blockDim.x) {
        int j = (int)(idx / N), n = (int)(idx % N);
        float v[2];
        #pragma unroll
        for (int e = 0; e < 2; e++) {
            int k = 2 * j + e, row = -1;
            if (k >= d1 && k < d1 + l1) row = s1 + (k - d1);
            else if (k >= d0 && k < d0 + l0) row = s0 + (k - d0);
            v[e] = (row < 0) ? 0.f : W[(size_t)row * N + n];
        }
        out[idx] = splitpack(v[0], v[1]);
    }
}

// ---------------- f_atoms -> packed ----------------
__global__ void pack_fa_kernel(const float* __restrict__ fa, uint2* __restrict__ out)
{
    long tot = (long)NA * JP_FA;
    for (long idx = (long)blockIdx.x * blockDim.x + threadIdx.x; idx < tot;
         idx += (long)gridDim.x * blockDim.x) {
        int n = (int)(idx / JP_FA), j = (int)(idx % JP_FA);
        int k0 = 2 * j;
        float v0 = (k0     < FD) ? fa[(size_t)n * FD + k0]     : 0.f;
        float v1 = (k0 + 1 < FD) ? fa[(size_t)n * FD + k0 + 1] : 0.f;
        out[idx] = splitpack(v0, v1);
    }
}

// ---------------- build X packed: rows (n*3+c), K layout [a(134)|self(134)] ----------------
__global__ void build_X_kernel(const float* __restrict__ f_atoms, const float* __restrict__ f_bonds,
                               const int* __restrict__ a2a, const int* __restrict__ a2b,
                               uint2* __restrict__ Xp)
{
    int n = blockIdx.x;
    __shared__ int   nb[KNB];
    __shared__ float bond[KNB][3];
    __shared__ float stg[6][134];
    if (threadIdx.x < KNB) {
        int k = threadIdx.x;
        nb[k] = a2a[n * KNB + k];
        int b = a2b[n * KNB + k];
        bond[k][0] = f_bonds[(size_t)b * 3 + 0];
        bond[k][1] = f_bonds[(size_t)b * 3 + 1];
        bond[k][2] = f_bonds[(size_t)b * 3 + 2];
    }
    if (threadIdx.x < 6) stg[threadIdx.x][133] = 0.f;
    __syncthreads();
    float ms0 = 0.f, ms1 = 0.f, ms2 = 0.f;
    #pragma unroll
    for (int k = 0; k < KNB; k++) {
        float mk = (nb[k] > 0) ? 1.f : 0.f;
        ms0 += mk * bond[k][0];
        ms1 += mk * bond[k][1];
        ms2 += mk * bond[k][2];
    }
    for (int f = threadIdx.x; f < FD; f += blockDim.x) {
        float selfv = f_atoms[(size_t)n * FD + f];
        float a0 = 0.f, a1 = 0.f, a2 = 0.f;
        #pragma unroll
        for (int k = 0; k < KNB; k++) {
            float fv = f_atoms[(size_t)nb[k] * FD + f];
            a0 += fv * bond[k][0];
            a1 += fv * bond[k][1];
            a2 += fv * bond[k][2];
        }
        stg[0][f] = a0; stg[1][f] = a1; stg[2][f] = a2;
        stg[3][f] = selfv * ms0; stg[4][f] = selfv * ms1; stg[5][f] = selfv * ms2;
    }
    __syncthreads();
    for (int t = threadIdx.x; t < 3 * JP_X; t += blockDim.x) {
        int c = t / JP_X, j = t % JP_X;
        float v[2];
        #pragma unroll
        for (int e = 0; e < 2; e++) {
            int k = 2 * j + e;
            if (k < 134)      v[e] = stg[c][k];
            else if (k < 268) v[e] = stg[3 + c][k - 134];
            else              v[e] = 0.f;
        }
        Xp[((size_t)n * 3 + c) * JP_X + j] = splitpack(v[0], v[1]);
    }
}

// ---------------- message-passing gather -> packed (float4 loads; invnorm fused) ----------------
__global__ void gather_kernel(const float* __restrict__ s, const float* __restrict__ v,
                              const int* __restrict__ a2a,
                              uint2* __restrict__ sagg_p, uint2* __restrict__ vagg_p)
{
    int n = blockIdx.x;
    __shared__ int nb[KNB];
    if (threadIdx.x < KNB) nb[threadIdx.x] = a2a[n * KNB + threadIdx.x];
    __syncthreads();
    int cnt = 0;
    #pragma unroll
    for (int k = 0; k < KNB; k++) cnt += (nb[k] > 0) ? 1 : 0;
    const float sc = 1.f / (float)max(cnt, 1);

    const float4* s4 = (const float4*)s;
    const float4* v4 = (const float4*)v;
    size_t b0 = (size_t)nb[0] * 275, b1 = (size_t)nb[1] * 275, b2 = (size_t)nb[2] * 275;
    size_t b3 = (size_t)nb[3] * 275, b4 = (size_t)nb[4] * 275, b5 = (size_t)nb[5] * 275;

    uint2* sd = sagg_p + (size_t)n * JP_H;
    for (int t = threadIdx.x; t < 280; t += blockDim.x) {
        if (t < 275) {
            float4 x0 = s4[b0+t], x1 = s4[b1+t], x2 = s4[b2+t];
            float4 x3 = s4[b3+t], x4 = s4[b4+t], x5 = s4[b5+t];
            float4 a;
            a.x = x0.x + x1.x + x2.x + x3.x + x4.x + x5.x;
            a.y = x0.y + x1.y + x2.y + x3.y + x4.y + x5.y;
            a.z = x0.z + x1.z + x2.z + x3.z + x4.z + x5.z;
            a.w = x0.w + x1.w + x2.w + x3.w + x4.w + x5.w;
            *(uint4*)(sd + 2 * t) = splitpack4(a);
        } else {
            *(uint4*)(sd + 550 + 2 * (t - 275)) = make_uint4(0, 0, 0, 0);
        }
    }
    size_t c0 = b0 * 3, c1 = b1 * 3, c2 = b2 * 3, c3 = b3 * 3, c4 = b4 * 3, c5 = b5 * 3;
    for (int t = threadIdx.x; t < 840; t += blockDim.x) {
        int c = t / 280, u = t % 280;
        uint2* dst = vagg_p + ((size_t)n * 3 + c) * JP_H;
        if (u < 275) {
            size_t e = (size_t)c * 275 + u;
            float4 x0 = v4[c0+e], x1 = v4[c1+e], x2 = v4[c2+e];
            float4 x3 = v4[c3+e], x4 = v4[c4+e], x5 = v4[c5+e];
            float4 a;
            a.x = (x0.x + x1.x + x2.x + x3.x + x4.x + x5.x) * sc;
            a.y = (x0.y + x1.y + x2.y + x3.y + x4.y + x5.y) * sc;
            a.z = (x0.z + x1.z + x2.z + x3.z + x4.z + x5.z) * sc;
            a.w = (x0.w + x1.w + x2.w + x3.w + x4.w + x5.w) * sc;
            *(uint4*)(dst + 2 * u) = splitpack4(a);
        } else {
            *(uint4*)(dst + 550 + 2 * (u - 275)) = make_uint4(0, 0, 0, 0);
        }
    }
}

// ---------------- output-stage concat builders (gather fused, float4) ----------------
__global__ void build_osin_kernel(const float* __restrict__ fa, const float* __restrict__ s,
                                  const int* __restrict__ a2a, uint2* __restrict__ osin_p)
{
    int n = blockIdx.x;
    __shared__ int nb[KNB];
    if (threadIdx.x < KNB) nb[threadIdx.x] = a2a[n * KNB + threadIdx.x];
    __syncthreads();
    const float4* s4 = (const float4*)s;
    size_t b0 = (size_t)nb[0] * 275, b1 = (size_t)nb[1] * 275, b2 = (size_t)nb[2] * 275;
    size_t b3 = (size_t)nb[3] * 275, b4 = (size_t)nb[4] * 275, b5 = (size_t)nb[5] * 275;
    uint2* dst = osin_p + (size_t)n * JP_OS;
    for (int t = threadIdx.x; t < 67 + 275 + 7; t += blockDim.x) {
        if (t < 67) {
            int k0 = 2 * t;
            float v0 = fa[(size_t)n * FD + k0];
            float v1 = (k0 + 1 < FD) ? fa[(size_t)n * FD + k0 + 1] : 0.f;
            dst[t] = splitpack(v0, v1);
        } else if (t < 342) {
            int w = t - 67;
            float4 x0 = s4[b0+w], x1 = s4[b1+w], x2 = s4[b2+w];
            float4 x3 = s4[b3+w], x4 = s4[b4+w], x5 = s4[b5+w];
            float4 a;
            a.x = x0.x + x1.x + x2.x + x3.x + x4.x + x5.x;
            a.y = x0.y + x1.y + x2.y + x3.y + x4.y + x5.y;
            a.z = x0.z + x1.z + x2.z + x3.z + x4.z + x5.z;
            a.w = x0.w + x1.w + x2.w + x3.w + x4.w + x5.w;
            dst[67 + 2 * w] = splitpack(a.x, a.y);
            dst[68 + 2 * w] = splitpack(a.z, a.w);
        } else {
            dst[617 + (t - 342)] = make_uint2(0, 0);
        }
    }
}

__global__ void build_ovin_kernel(const float* __restrict__ vi, const float* __restrict__ v,
                                  const int* __restrict__ a2a, uint2* __restrict__ ovin_p)
{
    int n = blockIdx.x;
    __shared__ int nb[KNB];
    if (threadIdx.x < KNB) nb[threadIdx.x] = a2a[n * KNB + threadIdx.x];
    __syncthreads();
    const float4* vi4 = (const float4*)vi;
    const float4* v4  = (const float4*)v;
    size_t c0 = (size_t)nb[0] * 825, c1 = (size_t)nb[1] * 825, c2 = (size_t)nb[2] * 825;
    size_t c3 = (size_t)nb[3] * 825, c4 = (size_t)nb[4] * 825, c5 = (size_t)nb[5] * 825;
    for (int t = threadIdx.x; t < 3 * 552; t += blockDim.x) {
        int c = t / 552, u = t % 552;
        uint2* dst = ovin_p + ((size_t)n * 3 + c) * JP_OV;
        if (u < 275) {
            float4 x = vi4[((size_t)n * 3 + c) * 275 + u];
            *(uint4*)(dst + 2 * u) = splitpack4(x);
        } else if (u < 550) {
            int w = u - 275;
            size_t e = (size_t)c * 275 + w;
            float4 x0 = v4[c0+e], x1 = v4[c1+e], x2 = v4[c2+e];
            float4 x3 = v4[c3+e], x4 = v4[c4+e], x5 = v4[c5+e];
            float4 a;
            a.x = x0.x + x1.x + x2.x + x3.x + x4.x + x5.x;
            a.y = x0.y + x1.y + x2.y + x3.y + x4.y + x5.y;
            a.z = x0.z + x1.z + x2.z + x3.z + x4.z + x5.z;
            a.w = x0.w + x1.w + x2.w + x3.w + x4.w + x5.w;
            *(uint4*)(dst + 550 + 2 * w) = splitpack4(a);
        } else {
            *(uint4*)(dst + 1100 + 2 * (u - 550)) = make_uint4(0, 0, 0, 0);
        }
    }
}

// o[n] = [osb | sum_c ovb], float4
__global__ void build_o_kernel(const float* __restrict__ osb, const float* __restrict__ ovb,
                               float* __restrict__ o)
{
    const float4* osb4 = (const float4*)osb;   // row 175
    const float4* ovb4 = (const float4*)ovb;   // row 525
    float4* o4 = (float4*)o;                   // row 350
    long tot = (long)NA * 350;
    for (long idx = (long)blockIdx.x * blockDim.x + threadIdx.x; idx < tot;
         idx += (long)gridDim.x * blockDim.x) {
        int n = (int)(idx / 350);
        int j = (int)(idx % 350);
        float4 r;
        if (j < 175) {
            r = osb4[(size_t)n * 175 + j];
        } else {
            size_t b = (size_t)n * 525 + (j - 175);
            float4 x0 = ovb4[b], x1 = ovb4[b + 175], x2 = ovb4[b + 350];
            r.x = x0.x + x1.x + x2.x;
            r.y = x0.y + x1.y + x2.y;
            r.z = x0.z + x1.z + x2.z;
            r.w = x0.w + x1.w + x2.w;
        }
        o4[idx] = r;
    }
}

// ---------------- readout ----------------
__global__ void mol_start_kernel(const int* __restrict__ ids, int* __restrict__ start)
{
    int m = blockIdx.x * blockDim.x + threadIdx.x;
    if (m > NM) return;
    int lo = 0, hi = NA;
    while (lo < hi) {
        int mid = (lo + hi) >> 1;
        if (ids[mid] < m) lo = mid + 1; else hi = mid;
    }
    start[m] = lo;
}

__global__ void segment_mean_kernel(const float* __restrict__ o, const int* __restrict__ start,
                                    uint2* __restrict__ mol_p)
{
    int m = blockIdx.x;
    int s0 = start[m], e0 = start[m + 1];
    int cnt = e0 - s0;
    if (s0 == 0 && e0 > 0) cnt -= 1;   // atom 0 is padding
    float sc = 1.f / (float)max(cnt, 1);
    const float4* o4 = (const float4*)o;
    uint2* dst = mol_p + (size_t)m * JP_FF;
    for (int t = threadIdx.x; t < 352; t += blockDim.x) {
        if (t < 350) {
            float4 a = make_float4(0.f, 0.f, 0.f, 0.f);
            for (int n = s0; n < e0; n++) {
                if (n == 0) continue;
                float4 x = o4[(size_t)n * 350 + t];
                a.x += x.x; a.y += x.y; a.z += x.z; a.w += x.w;
            }
            a.x *= sc; a.y *= sc; a.z *= sc; a.w *= sc;
            *(uint4*)(dst + 2 * t) = splitpack4(a);
        } else {
            *(uint4*)(dst + 700 + 2 * (t - 350)) = make_uint4(0, 0, 0, 0);
        }
    }
}

__global__ void ffn_out_kernel(const float* __restrict__ h, const float* __restrict__ W2,
                               const float* __restrict__ b2, float* __restrict__ out)
{
    int m = blockIdx.x;
    float acc = 0.f;
    for (int j = threadIdx.x; j < FHD; j += 256) acc += h[m * FHD + j] * W2[j];
    __shared__ float red[256];
    red[threadIdx.x] = acc;
    __syncthreads();
    for (int st = 128; st > 0; st >>= 1) {
        if (threadIdx.x < st) red[threadIdx.x] += red[threadIdx.x + st];
        __syncthreads();
    }
    if (threadIdx.x == 0) out[m] = red[0] + b2[0];
}

// ---------------- launch ----------------
extern "C" void kernel_launch(void* const* d_in, const int* in_sizes, int n_in,
                              void* d_out, int out_size)
{
    const float* f_atoms = (const float*)d_in[0];
    const float* f_bonds = (const float*)d_in[1];
    const float* W_is    = (const float*)d_in[2];
    const float* W_iv    = (const float*)d_in[3];
    const float* W_hs    = (const float*)d_in[4];
    const float* W_hv    = (const float*)d_in[5];
    const float* W_os    = (const float*)d_in[6];
    const float* b_os    = (const float*)d_in[7];
    const float* W_ov    = (const float*)d_in[8];
    const float* b_ov    = (const float*)d_in[9];
    const float* ffn_W1  = (const float*)d_in[10];
    const float* ffn_b1  = (const float*)d_in[11];
    const float* ffn_W2  = (const float*)d_in[12];
    const float* ffn_b2  = (const float*)d_in[13];
    const int*   a2a     = (const int*)d_in[14];
    const int*   a2b     = (const int*)d_in[15];
    const int*   mol_ids = (const int*)d_in[16];
    float*       out     = (float*)d_out;

    uint2 *p_fa, *p_X, *p_sagg, *p_vagg, *p_osin, *p_ovin, *p_mol;
    uint2 *p_Wis, *p_Wiv, *p_Whs, *p_Whv, *p_Wos, *p_Wov, *p_Wff;
    float *p_si, *p_s, *p_vi, *p_v, *p_osb, *p_ovb, *p_o, *p_h;
    int* p_molstart;
    cudaGetSymbolAddress((void**)&p_fa,   g_fa_p);
    cudaGetSymbolAddress((void**)&p_X,    g_X_p);
    cudaGetSymbolAddress((void**)&p_sagg, g_sagg_p);
    cudaGetSymbolAddress((void**)&p_vagg, g_vagg_p);
    cudaGetSymbolAddress((void**)&p_osin, g_osin_p);
    cudaGetSymbolAddress((void**)&p_ovin, g_ovin_p);
    cudaGetSymbolAddress((void**)&p_mol,  g_mol_p);
    cudaGetSymbolAddress((void**)&p_Wis,  g_Wis_p);
    cudaGetSymbolAddress((void**)&p_Wiv,  g_Wiv_p);
    cudaGetSymbolAddress((void**)&p_Whs,  g_Whs_p);
    cudaGetSymbolAddress((void**)&p_Whv,  g_Whv_p);
    cudaGetSymbolAddress((void**)&p_Wos,  g_Wos_p);
    cudaGetSymbolAddress((void**)&p_Wov,  g_Wov_p);
    cudaGetSymbolAddress((void**)&p_Wff,  g_Wff_p);
    cudaGetSymbolAddress((void**)&p_si,   g_si);
    cudaGetSymbolAddress((void**)&p_s,    g_s);
    cudaGetSymbolAddress((void**)&p_vi,   g_vi);
    cudaGetSymbolAddress((void**)&p_v,    g_v);
    cudaGetSymbolAddress((void**)&p_osb,  g_osb);
    cudaGetSymbolAddress((void**)&p_ovb,  g_ovb);
    cudaGetSymbolAddress((void**)&p_o,    g_o);
    cudaGetSymbolAddress((void**)&p_h,    g_h);
    cudaGetSymbolAddress((void**)&p_molstart, g_molstart);

    cudaFuncSetAttribute(bgemm_kernel<true,false,false,true>,
                         cudaFuncAttributeMaxDynamicSharedMemorySize, SMEM_GEMM);
    cudaFuncSetAttribute(bgemm_kernel<true,true,false,false>,
                         cudaFuncAttributeMaxDynamicSharedMemorySize, SMEM_GEMM);
    cudaFuncSetAttribute(bgemm_kernel<true,false,true,false>,
                         cudaFuncAttributeMaxDynamicSharedMemorySize, SMEM_GEMM);

    const int tilesS = (NA + BMROW - 1) / BMROW;          // 79
    const int tilesV = (3 * NA + BMROW - 1) / BMROW;      // 235
    const int tilesM = (NM + BMROW - 1) / BMROW;          // 4

    // Launch order: index 5 (0-based) = fused si/vi GEMM, so ncu (-s 5 -c 1)
    // profiles the GEMM instead of packW.
    packW_kernel<<<512, 256>>>(W_is, HD, JP_FA, 0, 133, 0, 0, 0, 0, p_Wis);      // 0
    packW_kernel<<<512, 256>>>(W_iv, HD, JP_X, 0, 133, 0, 133, 133, 134, p_Wiv); // 1
    pack_fa_kernel<<<2048, 256>>>(f_atoms, p_fa);                                 // 2
    build_X_kernel<<<NA, 192>>>(f_atoms, f_bonds, a2a, a2b, p_X);                 // 3
    packW_kernel<<<1024, 256>>>(W_hs, HD, JP_H, 0, 1100, 0, 0, 0, 0, p_Whs);      // 4

    // 5: si & vi fused GEMM (profiled)
    {
        dim3 g((HD + 127) / 128, tilesS + tilesV);
        bgemm_kernel<true, false, false, true><<<g, 256, SMEM_GEMM>>>(
            p_fa, p_Wis, nullptr, nullptr, p_s, p_si, NA, 5, JP_FA,
            p_X,  p_Wiv, nullptr, nullptr, p_v, p_vi, 3 * NA, 9, JP_X,
            HD, tilesS);
    }

    packW_kernel<<<1024, 256>>>(W_hv, HD, JP_H, 0, 1100, 0, 0, 0, 0, p_Whv);
    packW_kernel<<<1024, 256>>>(W_os, FHD, JP_OS, 0, 133, 0, 133, 1100, 134, p_Wos);
    packW_kernel<<<1024, 256>>>(W_ov, FHD, JP_OV, 0, 2200, 0, 0, 0, 0, p_Wov);
    packW_kernel<<<1024, 256>>>(ffn_W1, FHD, JP_FF, 0, 1400, 0, 0, 0, 0, p_Wff);

    // message passing: s & v GEMMs fused per iteration
    for (int it = 0; it < 6; it++) {
        gather_kernel<<<NA, 256>>>(p_s, p_v, a2a, p_sagg, p_vagg);
        dim3 g((HD + 127) / 128, tilesS + tilesV);
        bgemm_kernel<true, true, false, false><<<g, 256, SMEM_GEMM>>>(
            p_sagg, p_Whs, p_si, nullptr, p_s, nullptr, NA, 35, JP_H,
            p_vagg, p_Whv, p_vi, nullptr, p_v, nullptr, 3 * NA, 35, JP_H,
            HD, tilesS);
    }

    // output stage: os & ov GEMMs fused
    build_osin_kernel<<<NA, 256>>>(f_atoms, p_s, a2a, p_osin);
    build_ovin_kernel<<<NA, 256>>>(p_vi, p_v, a2a, p_ovin);
    {
        dim3 g((FHD + 127) / 128, tilesS + tilesV);
        bgemm_kernel<true, false, true, false><<<g, 256, SMEM_GEMM>>>(
            p_osin, p_Wos, nullptr, b_os, p_osb, nullptr, NA, 39, JP_OS,
            p_ovin, p_Wov, nullptr, b_ov, p_ovb, nullptr, 3 * NA, 69, JP_OV,
            FHD, tilesS);
    }
    {
        long tot3 = (long)NA * 350;
        build_o_kernel<<<(unsigned)((tot3 + 255) / 256), 256>>>(p_osb, p_ovb, p_o);
    }

    // readout + FFN
    mol_start_kernel<<<4, 256>>>(mol_ids, p_molstart);
    segment_mean_kernel<<<NM, 256>>>(p_o, p_molstart, p_mol);
    {
        dim3 g((FHD + 127) / 128, tilesM);
        bgemm_kernel<true, false, true, false><<<g, 256, SMEM_GEMM>>>(
            p_mol, p_Wff, nullptr, ffn_b1, p_h, nullptr, NM, 44, JP_FF,
            p_mol, p_Wff, nullptr, ffn_b1, p_h, nullptr, NM, 44, JP_FF,
            FHD, tilesM);
    }
    ffn_out_kernel<<<NM, 256>>>(p_h, ffn_W2, ffn_b2, out);
}

// round 15
// speedup vs baseline: 1.1595x; 1.1595x over previous
#include <cuda_runtime.h>
#include <cstdint>

// ---------------- Problem constants ----------------
#define NA   20001
#define FD   133
#define KNB  6
#define HD   1100
#define FHD  700
#define NM   800
#define FFK  1400

// K paddings in PAIRS (bf16x2). Multiples of 16 pairs = 32 elems (one stage).
#define JP_FA   80      // si : T=5
#define JP_X    144     // vi : T=9
#define JP_H    560     // hs/hv : T=35
#define JP_OS   624     // os : T=39
#define JP_OV   1104    // ov : T=69
#define JP_FF   704     // ffn : T=44

// ---------------- Scratch (device globals) ----------------
__device__ __align__(16) uint2 g_fa_p  [(size_t)NA * JP_FA];
__device__ __align__(16) uint2 g_X_p   [(size_t)NA * 3 * JP_X];
__device__ __align__(16) uint2 g_sagg_p[(size_t)NA * JP_H];
__device__ __align__(16) uint2 g_vagg_p[(size_t)NA * 3 * JP_H];
__device__ __align__(16) uint2 g_osin_p[(size_t)NA * JP_OS];
__device__ __align__(16) uint2 g_ovin_p[(size_t)NA * 3 * JP_OV];
__device__ __align__(16) uint2 g_mol_p [(size_t)NM * JP_FF];

__device__ __align__(16) uint2 g_Wis_p [(size_t)JP_FA * HD];
__device__ __align__(16) uint2 g_Wiv_p [(size_t)JP_X  * HD];
__device__ __align__(16) uint2 g_Whs_p [(size_t)JP_H  * HD];
__device__ __align__(16) uint2 g_Whv_p [(size_t)JP_H  * HD];
__device__ __align__(16) uint2 g_Wos_p [(size_t)JP_OS * FHD];
__device__ __align__(16) uint2 g_Wov_p [(size_t)JP_OV * FHD];
__device__ __align__(16) uint2 g_Wff_p [(size_t)JP_FF * FHD];

__device__ __align__(16) float g_si [(size_t)NA * HD];
__device__ __align__(16) float g_s  [(size_t)NA * HD];
__device__ __align__(16) float g_vi [(size_t)NA * 3 * HD];
__device__ __align__(16) float g_v  [(size_t)NA * 3 * HD];
__device__ __align__(16) float g_osb[(size_t)NA * FHD];
__device__ __align__(16) float g_ovb[(size_t)NA * 3 * FHD];
__device__ __align__(16) float g_o  [(size_t)NA * FFK];
__device__ __align__(16) float g_h  [NM * FHD];
__device__ int g_molstart[NM + 1];

// ---------------- bf16 split-pack helper ----------------
__device__ __forceinline__ uint2 splitpack(float x0, float x1) {
    unsigned h;
    asm("cvt.rn.bf16x2.f32 %0, %1, %2;" : "=r"(h) : "f"(x1), "f"(x0));
    float h0 = __uint_as_float(h << 16);
    float h1 = __uint_as_float(h & 0xFFFF0000u);
    unsigned l;
    asm("cvt.rn.bf16x2.f32 %0, %1, %2;" : "=r"(l) : "f"(x1 - h1), "f"(x0 - h0));
    return make_uint2(h, l);
}

__device__ __forceinline__ uint4 splitpack4(float4 a) {
    uint2 r0 = splitpack(a.x, a.y);
    uint2 r1 = splitpack(a.z, a.w);
    return make_uint4(r0.x, r0.y, r1.x, r1.y);
}

__device__ __forceinline__ void cp16(void* dst_smem, const void* src, int bytes) {
    unsigned sa = (unsigned)__cvta_generic_to_shared(dst_smem);
    asm volatile("cp.async.ca.shared.global [%0], [%1], 16, %2;\n"
                 :: "r"(sa), "l"(src), "r"(bytes));
}

#define MMA_BF16(ACC, AF, BF)                                                   \
    asm volatile(                                                               \
        "mma.sync.aligned.m16n8k16.row.col.f32.bf16.bf16.f32 "                  \
        "{%0,%1,%2,%3}, {%4,%5,%6,%7}, {%8,%9}, {%0,%1,%2,%3};\n"               \
        : "+f"(ACC[0]), "+f"(ACC[1]), "+f"(ACC[2]), "+f"(ACC[3])                \
        : "r"(AF[0]), "r"(AF[1]), "r"(AF[2]), "r"(AF[3]),                       \
          "r"(BF[0]), "r"(BF[1]))

// ---------------- bf16x3 dual-problem GEMM, 128x128 tile ----------------
// blockIdx.y < tiles0 -> problem 0, else problem 1 (row tile (y - tiles0)).
// BK=32/stage, double-buffered, one __syncthreads per stage (load for t+1
// issued after the barrier; overwrite target is the buffer stage t-1 used).
#define ASTP 18
#define BSTP 132
#define STG_A (128 * ASTP)            // uint2
#define STG_B (16 * BSTP)             // uint2
#define STG_U2 (STG_A + STG_B)        // 4416 uint2 = 35328 B
#define SMEM_GEMM (2 * STG_U2 * 8)    // 70656 B

template<bool RELU, bool HAS_ADD, bool HAS_BIAS, bool WRITE_RAW>
__global__ __launch_bounds__(256, 2)
void bgemm_kernel(const uint2* __restrict__ A0, const uint2* __restrict__ B0,
                  const float* __restrict__ Add0, const float* __restrict__ bias0,
                  float* __restrict__ C0, float* __restrict__ Craw0,
                  int M0, int T0, int ldp0,
                  const uint2* __restrict__ A1, const uint2* __restrict__ B1,
                  const float* __restrict__ Add1, const float* __restrict__ bias1,
                  float* __restrict__ C1, float* __restrict__ Craw1,
                  int M1, int T1, int ldp1,
                  int N, int tiles0)
{
    extern __shared__ __align__(16) uint2 smem_u2[];

    const bool p1 = (int)blockIdx.y >= tiles0;
    const uint2* __restrict__ A   = p1 ? A1   : A0;
    const uint2* __restrict__ B   = p1 ? B1   : B0;
    const float* __restrict__ Add = p1 ? Add1 : Add0;
    const float* __restrict__ bias= p1 ? bias1: bias0;
    float* __restrict__ C    = p1 ? C1    : C0;
    float* __restrict__ Craw = p1 ? Craw1 : Craw0;
    const int M   = p1 ? M1   : M0;
    const int T   = p1 ? T1   : T0;
    const int ldp = p1 ? ldp1 : ldp0;
    const int rowBase = (p1 ? ((int)blockIdx.y - tiles0) : (int)blockIdx.y) * 128;

    const int tid = threadIdx.x;
    const int colBase = blockIdx.x * 128;
    const int warpId = tid >> 5;
    const int lane = tid & 31;
    const int g  = lane >> 2;
    const int tg = lane & 3;
    const int wm = (warpId & 1) * 64;
    const int wn = (warpId >> 1) * 32;

    float acc[4][4][4];
    #pragma unroll
    for (int mi = 0; mi < 4; mi++)
        #pragma unroll
        for (int ni = 0; ni < 4; ni++)
            #pragma unroll
            for (int j = 0; j < 4; j++) acc[mi][ni][j] = 0.f;

    auto load_stage = [&](int t, int st) {
        uint2* As = smem_u2 + st * STG_U2;
        uint2* Bs = As + STG_A;
        #pragma unroll
        for (int i = 0; i < 4; i++) {
            int c = tid + i * 256;
            int m = c >> 3, q = c & 7;
            int gm = rowBase + m;
            bool ok = gm < M;
            const uint2* src = ok ? (A + (size_t)gm * ldp + t * 16 + q * 2) : A;
            cp16(&As[m * ASTP + q * 2], src, ok ? 16 : 0);
        }
        #pragma unroll
        for (int i = 0; i < 4; i++) {
            int c = tid + i * 256;
            int j = c >> 6, q = c & 63;
            int gn = colBase + q * 2;
            bool ok = gn < N;
            const uint2* src = ok ? (B + (size_t)(t * 16 + j) * N + gn) : B;
            cp16(&Bs[j * BSTP + q * 2], src, ok ? 16 : 0);
        }
        asm volatile("cp.async.commit_group;\n");
    };

    load_stage(0, 0);

    for (int t = 0; t < T; t++) {
        const int st = t & 1;
        asm volatile("cp.async.wait_group 0;\n");
        __syncthreads();

        if (t + 1 < T) load_stage(t + 1, st ^ 1);

        const uint2* As = smem_u2 + st * STG_U2;
        const uint2* Bs = As + STG_A;

        #pragma unroll
        for (int ks = 0; ks < 2; ks++) {
            const int kb = ks * 8;
            unsigned ah[4][4], al[4][4], bh[4][2], bl[4][2];
            #pragma unroll
            for (int mi = 0; mi < 4; mi++) {
                int r = wm + mi * 16 + g;
                uint2 p0 = As[r * ASTP + kb + tg];
                uint2 q1 = As[(r + 8) * ASTP + kb + tg];
                uint2 p2 = As[r * ASTP + kb + 4 + tg];
                uint2 p3 = As[(r + 8) * ASTP + kb + 4 + tg];
                ah[mi][0] = p0.x; ah[mi][1] = q1.x; ah[mi][2] = p2.x; ah[mi][3] = p3.x;
                al[mi][0] = p0.y; al[mi][1] = q1.y; al[mi][2] = p2.y; al[mi][3] = p3.y;
            }
            #pragma unroll
            for (int ni = 0; ni < 4; ni++) {
                int n = wn + ni * 8 + g;
                uint2 q0 = Bs[(kb + tg) * BSTP + n];
                uint2 q1 = Bs[(kb + 4 + tg) * BSTP + n];
                bh[ni][0] = q0.x; bh[ni][1] = q1.x;
                bl[ni][0] = q0.y; bl[ni][1] = q1.y;
            }
            #pragma unroll
            for (int mi = 0; mi < 4; mi++)
                #pragma unroll
                for (int ni = 0; ni < 4; ni++) {
                    MMA_BF16(acc[mi][ni], ah[mi], bl[ni]);   // hi*lo
                    MMA_BF16(acc[mi][ni], al[mi], bh[ni]);   // lo*hi
                    MMA_BF16(acc[mi][ni], ah[mi], bh[ni]);   // hi*hi last
                }
        }
    }

    #pragma unroll
    for (int mi = 0; mi < 4; mi++) {
        int r0 = rowBase + wm + mi * 16 + g;
        #pragma unroll
        for (int ni = 0; ni < 4; ni++) {
            int cN = colBase + wn + ni * 8 + tg * 2;
            if (cN >= N) continue;
            #pragma unroll
            for (int half = 0; half < 2; half++) {
                int r = r0 + half * 8;
                if (r >= M) continue;
                size_t idx = (size_t)r * N + cN;
                float2 vv;
                vv.x = acc[mi][ni][half * 2 + 0];
                vv.y = acc[mi][ni][half * 2 + 1];
                if (HAS_ADD) {
                    float2 a = *(const float2*)(Add + idx);
                    vv.x += a.x; vv.y += a.y;
                }
                if (HAS_BIAS) {
                    float2 b = *(const float2*)(bias + cN);
                    vv.x += b.x; vv.y += b.y;
                }
                if (WRITE_RAW) *(float2*)(Craw + idx) = vv;
                if (RELU) { vv.x = fmaxf(vv.x, 0.f); vv.y = fmaxf(vv.y, 0.f); }
                *(float2*)(C + idx) = vv;
            }
        }
    }
}

// ---------------- weight split-pack (2-segment k remap), layout [j][n] ----------------
__global__ void packW_kernel(const float* __restrict__ W, int N, int Jtot,
                             int s0, int l0, int d0, int s1, int l1, int d1,
                             uint2* __restrict__ out)
{
    long tot = (long)Jtot * N;
    for (long idx = (long)blockIdx.x * blockDim.x + threadIdx.x; idx < tot;
         idx += (long)gridDim.x * blockDim.x) {
        int j = (int)(idx / N), n = (int)(idx % N);
        float v[2];
        #pragma unroll
        for (int e = 0; e < 2; e++) {
            int k = 2 * j + e, row = -1;
            if (k >= d1 && k < d1 + l1) row = s1 + (k - d1);
            else if (k >= d0 && k < d0 + l0) row = s0 + (k - d0);
            v[e] = (row < 0) ? 0.f : W[(size_t)row * N + n];
        }
        out[idx] = splitpack(v[0], v[1]);
    }
}

// ---------------- f_atoms -> packed ----------------
__global__ void pack_fa_kernel(const float* __restrict__ fa, uint2* __restrict__ out)
{
    long tot = (long)NA * JP_FA;
    for (long idx = (long)blockIdx.x * blockDim.x + threadIdx.x; idx < tot;
         idx += (long)gridDim.x * blockDim.x) {
        int n = (int)(idx / JP_FA), j = (int)(idx % JP_FA);
        int k0 = 2 * j;
        float v0 = (k0     < FD) ? fa[(size_t)n * FD + k0]     : 0.f;
        float v1 = (k0 + 1 < FD) ? fa[(size_t)n * FD + k0 + 1] : 0.f;
        out[idx] = splitpack(v0, v1);
    }
}

// ---------------- build X packed: rows (n*3+c), K layout [a(134)|self(134)] ----------------
__global__ void build_X_kernel(const float* __restrict__ f_atoms, const float* __restrict__ f_bonds,
                               const int* __restrict__ a2a, const int* __restrict__ a2b,
                               uint2* __restrict__ Xp)
{
    int n = blockIdx.x;
    __shared__ int   nb[KNB];
    __shared__ float bond[KNB][3];
    __shared__ float stg[6][134];
    if (threadIdx.x < KNB) {
        int k = threadIdx.x;
        nb[k] = a2a[n * KNB + k];
        int b = a2b[n * KNB + k];
        bond[k][0] = f_bonds[(size_t)b * 3 + 0];
        bond[k][1] = f_bonds[(size_t)b * 3 + 1];
        bond[k][2] = f_bonds[(size_t)b * 3 + 2];
    }
    if (threadIdx.x < 6) stg[threadIdx.x][133] = 0.f;
    __syncthreads();
    float ms0 = 0.f, ms1 = 0.f, ms2 = 0.f;
    #pragma unroll
    for (int k = 0; k < KNB; k++) {
        float mk = (nb[k] > 0) ? 1.f : 0.f;
        ms0 += mk * bond[k][0];
        ms1 += mk * bond[k][1];
        ms2 += mk * bond[k][2];
    }
    for (int f = threadIdx.x; f < FD; f += blockDim.x) {
        float selfv = f_atoms[(size_t)n * FD + f];
        float a0 = 0.f, a1 = 0.f, a2 = 0.f;
        #pragma unroll
        for (int k = 0; k < KNB; k++) {
            float fv = f_atoms[(size_t)nb[k] * FD + f];
            a0 += fv * bond[k][0];
            a1 += fv * bond[k][1];
            a2 += fv * bond[k][2];
        }
        stg[0][f] = a0; stg[1][f] = a1; stg[2][f] = a2;
        stg[3][f] = selfv * ms0; stg[4][f] = selfv * ms1; stg[5][f] = selfv * ms2;
    }
    __syncthreads();
    for (int t = threadIdx.x; t < 3 * JP_X; t += blockDim.x) {
        int c = t / JP_X, j = t % JP_X;
        float v[2];
        #pragma unroll
        for (int e = 0; e < 2; e++) {
            int k = 2 * j + e;
            if (k < 134)      v[e] = stg[c][k];
            else if (k < 268) v[e] = stg[3 + c][k - 134];
            else              v[e] = 0.f;
        }
        Xp[((size_t)n * 3 + c) * JP_X + j] = splitpack(v[0], v[1]);
    }
}

// ---------------- message-passing gather -> packed (float4 loads; invnorm fused) ----------------
__global__ void gather_kernel(const float* __restrict__ s, const float* __restrict__ v,
                              const int* __restrict__ a2a,
                              uint2* __restrict__ sagg_p, uint2* __restrict__ vagg_p)
{
    int n = blockIdx.x;
    __shared__ int nb[KNB];
    if (threadIdx.x < KNB) nb[threadIdx.x] = a2a[n * KNB + threadIdx.x];
    __syncthreads();
    int cnt = 0;
    #pragma unroll
    for (int k = 0; k < KNB; k++) cnt += (nb[k] > 0) ? 1 : 0;
    const float sc = 1.f / (float)max(cnt, 1);

    const float4* s4 = (const float4*)s;
    const float4* v4 = (const float4*)v;
    size_t b0 = (size_t)nb[0] * 275, b1 = (size_t)nb[1] * 275, b2 = (size_t)nb[2] * 275;
    size_t b3 = (size_t)nb[3] * 275, b4 = (size_t)nb[4] * 275, b5 = (size_t)nb[5] * 275;

    uint2* sd = sagg_p + (size_t)n * JP_H;
    for (int t = threadIdx.x; t < 280; t += blockDim.x) {
        if (t < 275) {
            float4 x0 = s4[b0+t], x1 = s4[b1+t], x2 = s4[b2+t];
            float4 x3 = s4[b3+t], x4 = s4[b4+t], x5 = s4[b5+t];
            float4 a;
            a.x = x0.x + x1.x + x2.x + x3.x + x4.x + x5.x;
            a.y = x0.y + x1.y + x2.y + x3.y + x4.y + x5.y;
            a.z = x0.z + x1.z + x2.z + x3.z + x4.z + x5.z;
            a.w = x0.w + x1.w + x2.w + x3.w + x4.w + x5.w;
            *(uint4*)(sd + 2 * t) = splitpack4(a);
        } else {
            *(uint4*)(sd + 550 + 2 * (t - 275)) = make_uint4(0, 0, 0, 0);
        }
    }
    size_t c0 = b0 * 3, c1 = b1 * 3, c2 = b2 * 3, c3 = b3 * 3, c4 = b4 * 3, c5 = b5 * 3;
    for (int t = threadIdx.x; t < 840; t += blockDim.x) {
        int c = t / 280, u = t % 280;
        uint2* dst = vagg_p + ((size_t)n * 3 + c) * JP_H;
        if (u < 275) {
            size_t e = (size_t)c * 275 + u;
            float4 x0 = v4[c0+e], x1 = v4[c1+e], x2 = v4[c2+e];
            float4 x3 = v4[c3+e], x4 = v4[c4+e], x5 = v4[c5+e];
            float4 a;
            a.x = (x0.x + x1.x + x2.x + x3.x + x4.x + x5.x) * sc;
            a.y = (x0.y + x1.y + x2.y + x3.y + x4.y + x5.y) * sc;
            a.z = (x0.z + x1.z + x2.z + x3.z + x4.z + x5.z) * sc;
            a.w = (x0.w + x1.w + x2.w + x3.w + x4.w + x5.w) * sc;
            *(uint4*)(dst + 2 * u) = splitpack4(a);
        } else {
            *(uint4*)(dst + 550 + 2 * (u - 275)) = make_uint4(0, 0, 0, 0);
        }
    }
}

// ---------------- output-stage concat builders (gather fused, float4) ----------------
__global__ void build_osin_kernel(const float* __restrict__ fa, const float* __restrict__ s,
                                  const int* __restrict__ a2a, uint2* __restrict__ osin_p)
{
    int n = blockIdx.x;
    __shared__ int nb[KNB];
    if (threadIdx.x < KNB) nb[threadIdx.x] = a2a[n * KNB + threadIdx.x];
    __syncthreads();
    const float4* s4 = (const float4*)s;
    size_t b0 = (size_t)nb[0] * 275, b1 = (size_t)nb[1] * 275, b2 = (size_t)nb[2] * 275;
    size_t b3 = (size_t)nb[3] * 275, b4 = (size_t)nb[4] * 275, b5 = (size_t)nb[5] * 275;
    uint2* dst = osin_p + (size_t)n * JP_OS;
    for (int t = threadIdx.x; t < 67 + 275 + 7; t += blockDim.x) {
        if (t < 67) {
            int k0 = 2 * t;
            float v0 = fa[(size_t)n * FD + k0];
            float v1 = (k0 + 1 < FD) ? fa[(size_t)n * FD + k0 + 1] : 0.f;
            dst[t] = splitpack(v0, v1);
        } else if (t < 342) {
            int w = t - 67;
            float4 x0 = s4[b0+w], x1 = s4[b1+w], x2 = s4[b2+w];
            float4 x3 = s4[b3+w], x4 = s4[b4+w], x5 = s4[b5+w];
            float4 a;
            a.x = x0.x + x1.x + x2.x + x3.x + x4.x + x5.x;
            a.y = x0.y + x1.y + x2.y + x3.y + x4.y + x5.y;
            a.z = x0.z + x1.z + x2.z + x3.z + x4.z + x5.z;
            a.w = x0.w + x1.w + x2.w + x3.w + x4.w + x5.w;
            dst[67 + 2 * w] = splitpack(a.x, a.y);
            dst[68 + 2 * w] = splitpack(a.z, a.w);
        } else {
            dst[617 + (t - 342)] = make_uint2(0, 0);
        }
    }
}

__global__ void build_ovin_kernel(const float* __restrict__ vi, const float* __restrict__ v,
                                  const int* __restrict__ a2a, uint2* __restrict__ ovin_p)
{
    int n = blockIdx.x;
    __shared__ int nb[KNB];
    if (threadIdx.x < KNB) nb[threadIdx.x] = a2a[n * KNB + threadIdx.x];
    __syncthreads();
    const float4* vi4 = (const float4*)vi;
    const float4* v4  = (const float4*)v;
    size_t c0 = (size_t)nb[0] * 825, c1 = (size_t)nb[1] * 825, c2 = (size_t)nb[2] * 825;
    size_t c3 = (size_t)nb[3] * 825, c4 = (size_t)nb[4] * 825, c5 = (size_t)nb[5] * 825;
    for (int t = threadIdx.x; t < 3 * 552; t += blockDim.x) {
        int c = t / 552, u = t % 552;
        uint2* dst = ovin_p + ((size_t)n * 3 + c) * JP_OV;
        if (u < 275) {
            float4 x = vi4[((size_t)n * 3 + c) * 275 + u];
            *(uint4*)(dst + 2 * u) = splitpack4(x);
        } else if (u < 550) {
            int w = u - 275;
            size_t e = (size_t)c * 275 + w;
            float4 x0 = v4[c0+e], x1 = v4[c1+e], x2 = v4[c2+e];
            float4 x3 = v4[c3+e], x4 = v4[c4+e], x5 = v4[c5+e];
            float4 a;
            a.x = x0.x + x1.x + x2.x + x3.x + x4.x + x5.x;
            a.y = x0.y + x1.y + x2.y + x3.y + x4.y + x5.y;
            a.z = x0.z + x1.z + x2.z + x3.z + x4.z + x5.z;
            a.w = x0.w + x1.w + x2.w + x3.w + x4.w + x5.w;
            *(uint4*)(dst + 550 + 2 * w) = splitpack4(a);
        } else {
            *(uint4*)(dst + 1100 + 2 * (u - 550)) = make_uint4(0, 0, 0, 0);
        }
    }
}

// o[n] = [osb | sum_c ovb], float4
__global__ void build_o_kernel(const float* __restrict__ osb, const float* __restrict__ ovb,
                               float* __restrict__ o)
{
    const float4* osb4 = (const float4*)osb;   // row 175
    const float4* ovb4 = (const float4*)ovb;   // row 525
    float4* o4 = (float4*)o;                   // row 350
    long tot = (long)NA * 350;
    for (long idx = (long)blockIdx.x * blockDim.x + threadIdx.x; idx < tot;
         idx += (long)gridDim.x * blockDim.x) {
        int n = (int)(idx / 350);
        int j = (int)(idx % 350);
        float4 r;
        if (j < 175) {
            r = osb4[(size_t)n * 175 + j];
        } else {
            size_t b = (size_t)n * 525 + (j - 175);
            float4 x0 = ovb4[b], x1 = ovb4[b + 175], x2 = ovb4[b + 350];
            r.x = x0.x + x1.x + x2.x;
            r.y = x0.y + x1.y + x2.y;
            r.z = x0.z + x1.z + x2.z;
            r.w = x0.w + x1.w + x2.w;
        }
        o4[idx] = r;
    }
}

// ---------------- readout ----------------
__global__ void mol_start_kernel(const int* __restrict__ ids, int* __restrict__ start)
{
    int m = blockIdx.x * blockDim.x + threadIdx.x;
    if (m > NM) return;
    int lo = 0, hi = NA;
    while (lo < hi) {
        int mid = (lo + hi) >> 1;
        if (ids[mid] < m) lo = mid + 1; else hi = mid;
    }
    start[m] = lo;
}

__global__ void segment_mean_kernel(const float* __restrict__ o, const int* __restrict__ start,
                                    uint2* __restrict__ mol_p)
{
    int m = blockIdx.x;
    int s0 = start[m], e0 = start[m + 1];
    int cnt = e0 - s0;
    if (s0 == 0 && e0 > 0) cnt -= 1;   // atom 0 is padding
    float sc = 1.f / (float)max(cnt, 1);
    const float4* o4 = (const float4*)o;
    uint2* dst = mol_p + (size_t)m * JP_FF;
    for (int t = threadIdx.x; t < 352; t += blockDim.x) {
        if (t < 350) {
            float4 a = make_float4(0.f, 0.f, 0.f, 0.f);
            for (int n = s0; n < e0; n++) {
                if (n == 0) continue;
                float4 x = o4[(size_t)n * 350 + t];
                a.x += x.x; a.y += x.y; a.z += x.z; a.w += x.w;
            }
            a.x *= sc; a.y *= sc; a.z *= sc; a.w *= sc;
            *(uint4*)(dst + 2 * t) = splitpack4(a);
        } else {
            *(uint4*)(dst + 700 + 2 * (t - 350)) = make_uint4(0, 0, 0, 0);
        }
    }
}

__global__ void ffn_out_kernel(const float* __restrict__ h, const float* __restrict__ W2,
                               const float* __restrict__ b2, float* __restrict__ out)
{
    int m = blockIdx.x;
    float acc = 0.f;
    for (int j = threadIdx.x; j < FHD; j += 256) acc += h[m * FHD + j] * W2[j];
    __shared__ float red[256];
    red[threadIdx.x] = acc;
    __syncthreads();
    for (int st = 128; st > 0; st >>= 1) {
        if (threadIdx.x < st) red[threadIdx.x] += red[threadIdx.x + st];
        __syncthreads();
    }
    if (threadIdx.x == 0) out[m] = red[0] + b2[0];
}

// ---------------- launch ----------------
extern "C" void kernel_launch(void* const* d_in, const int* in_sizes, int n_in,
                              void* d_out, int out_size)
{
    const float* f_atoms = (const float*)d_in[0];
    const float* f_bonds = (const float*)d_in[1];
    const float* W_is    = (const float*)d_in[2];
    const float* W_iv    = (const float*)d_in[3];
    const float* W_hs    = (const float*)d_in[4];
    const float* W_hv    = (const float*)d_in[5];
    const float* W_os    = (const float*)d_in[6];
    const float* b_os    = (const float*)d_in[7];
    const float* W_ov    = (const float*)d_in[8];
    const float* b_ov    = (const float*)d_in[9];
    const float* ffn_W1  = (const float*)d_in[10];
    const float* ffn_b1  = (const float*)d_in[11];
    const float* ffn_W2  = (const float*)d_in[12];
    const float* ffn_b2  = (const float*)d_in[13];
    const int*   a2a     = (const int*)d_in[14];
    const int*   a2b     = (const int*)d_in[15];
    const int*   mol_ids = (const int*)d_in[16];
    float*       out     = (float*)d_out;

    uint2 *p_fa, *p_X, *p_sagg, *p_vagg, *p_osin, *p_ovin, *p_mol;
    uint2 *p_Wis, *p_Wiv, *p_Whs, *p_Whv, *p_Wos, *p_Wov, *p_Wff;
    float *p_si, *p_s, *p_vi, *p_v, *p_osb, *p_ovb, *p_o, *p_h;
    int* p_molstart;
    cudaGetSymbolAddress((void**)&p_fa,   g_fa_p);
    cudaGetSymbolAddress((void**)&p_X,    g_X_p);
    cudaGetSymbolAddress((void**)&p_sagg, g_sagg_p);
    cudaGetSymbolAddress((void**)&p_vagg, g_vagg_p);
    cudaGetSymbolAddress((void**)&p_osin, g_osin_p);
    cudaGetSymbolAddress((void**)&p_ovin, g_ovin_p);
    cudaGetSymbolAddress((void**)&p_mol,  g_mol_p);
    cudaGetSymbolAddress((void**)&p_Wis,  g_Wis_p);
    cudaGetSymbolAddress((void**)&p_Wiv,  g_Wiv_p);
    cudaGetSymbolAddress((void**)&p_Whs,  g_Whs_p);
    cudaGetSymbolAddress((void**)&p_Whv,  g_Whv_p);
    cudaGetSymbolAddress((void**)&p_Wos,  g_Wos_p);
    cudaGetSymbolAddress((void**)&p_Wov,  g_Wov_p);
    cudaGetSymbolAddress((void**)&p_Wff,  g_Wff_p);
    cudaGetSymbolAddress((void**)&p_si,   g_si);
    cudaGetSymbolAddress((void**)&p_s,    g_s);
    cudaGetSymbolAddress((void**)&p_vi,   g_vi);
    cudaGetSymbolAddress((void**)&p_v,    g_v);
    cudaGetSymbolAddress((void**)&p_osb,  g_osb);
    cudaGetSymbolAddress((void**)&p_ovb,  g_ovb);
    cudaGetSymbolAddress((void**)&p_o,    g_o);
    cudaGetSymbolAddress((void**)&p_h,    g_h);
    cudaGetSymbolAddress((void**)&p_molstart, g_molstart);

    cudaFuncSetAttribute(bgemm_kernel<true,false,false,true>,
                         cudaFuncAttributeMaxDynamicSharedMemorySize, SMEM_GEMM);
    cudaFuncSetAttribute(bgemm_kernel<true,true,false,false>,
                         cudaFuncAttributeMaxDynamicSharedMemorySize, SMEM_GEMM);
    cudaFuncSetAttribute(bgemm_kernel<true,false,true,false>,
                         cudaFuncAttributeMaxDynamicSharedMemorySize, SMEM_GEMM);

    const int tilesS = (NA + 127) / 128;          // 157
    const int tilesV = (3 * NA + 127) / 128;      // 469
    const int tilesM = (NM + 127) / 128;          // 7

    // Launch order: index 5 (0-based) = fused si/vi GEMM (for ncu -s 5 -c 1).
    packW_kernel<<<512, 256>>>(W_is, HD, JP_FA, 0, 133, 0, 0, 0, 0, p_Wis);      // 0
    packW_kernel<<<512, 256>>>(W_iv, HD, JP_X, 0, 133, 0, 133, 133, 134, p_Wiv); // 1
    pack_fa_kernel<<<2048, 256>>>(f_atoms, p_fa);                                 // 2
    build_X_kernel<<<NA, 192>>>(f_atoms, f_bonds, a2a, a2b, p_X);                 // 3
    packW_kernel<<<1024, 256>>>(W_hs, HD, JP_H, 0, 1100, 0, 0, 0, 0, p_Whs);      // 4

    // 5: si & vi fused GEMM (profiled)
    {
        dim3 g((HD + 127) / 128, tilesS + tilesV);
        bgemm_kernel<true, false, false, true><<<g, 256, SMEM_GEMM>>>(
            p_fa, p_Wis, nullptr, nullptr, p_s, p_si, NA, 5, JP_FA,
            p_X,  p_Wiv, nullptr, nullptr, p_v, p_vi, 3 * NA, 9, JP_X,
            HD, tilesS);
    }

    packW_kernel<<<1024, 256>>>(W_hv, HD, JP_H, 0, 1100, 0, 0, 0, 0, p_Whv);
    packW_kernel<<<1024, 256>>>(W_os, FHD, JP_OS, 0, 133, 0, 133, 1100, 134, p_Wos);
    packW_kernel<<<1024, 256>>>(W_ov, FHD, JP_OV, 0, 2200, 0, 0, 0, 0, p_Wov);
    packW_kernel<<<1024, 256>>>(ffn_W1, FHD, JP_FF, 0, 1400, 0, 0, 0, 0, p_Wff);

    // message passing: s & v GEMMs fused per iteration
    for (int it = 0; it < 6; it++) {
        gather_kernel<<<NA, 256>>>(p_s, p_v, a2a, p_sagg, p_vagg);
        dim3 g((HD + 127) / 128, tilesS + tilesV);
        bgemm_kernel<true, true, false, false><<<g, 256, SMEM_GEMM>>>(
            p_sagg, p_Whs, p_si, nullptr, p_s, nullptr, NA, 35, JP_H,
            p_vagg, p_Whv, p_vi, nullptr, p_v, nullptr, 3 * NA, 35, JP_H,
            HD, tilesS);
    }

    // output stage: os & ov GEMMs fused
    build_osin_kernel<<<NA, 256>>>(f_atoms, p_s, a2a, p_osin);
    build_ovin_kernel<<<NA, 256>>>(p_vi, p_v, a2a, p_ovin);
    {
        dim3 g((FHD + 127) / 128, tilesS + tilesV);
        bgemm_kernel<true, false, true, false><<<g, 256, SMEM_GEMM>>>(
            p_osin, p_Wos, nullptr, b_os, p_osb, nullptr, NA, 39, JP_OS,
            p_ovin, p_Wov, nullptr, b_ov, p_ovb, nullptr, 3 * NA, 69, JP_OV,
            FHD, tilesS);
    }
    {
        long tot3 = (long)NA * 350;
        build_o_kernel<<<(unsigned)((tot3 + 255) / 256), 256>>>(p_osb, p_ovb, p_o);
    }

    // readout + FFN
    mol_start_kernel<<<4, 256>>>(mol_ids, p_molstart);
    segment_mean_kernel<<<NM, 256>>>(p_o, p_molstart, p_mol);
    {
        dim3 g((FHD + 127) / 128, tilesM);
        bgemm_kernel<true, false, true, false><<<g, 256, SMEM_GEMM>>>(
            p_mol, p_Wff, nullptr, ffn_b1, p_h, nullptr, NM, 44, JP_FF,
            p_mol, p_Wff, nullptr, ffn_b1, p_h, nullptr, NM, 44, JP_FF,
            FHD, tilesM);
    }
    ffn_out_kernel<<<NM, 256>>>(p_h, ffn_W2, ffn_b2, out);
}

// round 17
// speedup vs baseline: 1.1818x; 1.0192x over previous
#include <cuda_runtime.h>
#include <cstdint>

// ---------------- Problem constants ----------------
#define NA   20001
#define FD   133
#define KNB  6
#define HD   1100
#define FHD  700
#define NM   800
#define FFK  1400

// K paddings in PAIRS (bf16x2). Multiples of 16 pairs = 32 elems (one stage).
#define JP_FA   80      // si : T=5
#define JP_X    144     // vi : T=9
#define JP_H    560     // hs/hv : T=35
#define JP_OS   624     // os : T=39
#define JP_OV   1104    // ov : T=69
#define JP_FF   704     // ffn : T=44

// ---------------- Scratch (device globals) ----------------
__device__ __align__(16) uint2 g_fa_p  [(size_t)NA * JP_FA];
__device__ __align__(16) uint2 g_X_p   [(size_t)NA * 3 * JP_X];
__device__ __align__(16) uint2 g_sagg_p[(size_t)NA * JP_H];
__device__ __align__(16) uint2 g_vagg_p[(size_t)NA * 3 * JP_H];
__device__ __align__(16) uint2 g_osin_p[(size_t)NA * JP_OS];
__device__ __align__(16) uint2 g_ovin_p[(size_t)NA * 3 * JP_OV];
__device__ __align__(16) uint2 g_mol_p [(size_t)NM * JP_FF];

__device__ __align__(16) uint2 g_Wis_p [(size_t)JP_FA * HD];
__device__ __align__(16) uint2 g_Wiv_p [(size_t)JP_X  * HD];
__device__ __align__(16) uint2 g_Whs_p [(size_t)JP_H  * HD];
__device__ __align__(16) uint2 g_Whv_p [(size_t)JP_H  * HD];
__device__ __align__(16) uint2 g_Wos_p [(size_t)JP_OS * FHD];
__device__ __align__(16) uint2 g_Wov_p [(size_t)JP_OV * FHD];
__device__ __align__(16) uint2 g_Wff_p [(size_t)JP_FF * FHD];

__device__ __align__(16) float g_si [(size_t)NA * HD];
__device__ __align__(16) float g_s  [(size_t)NA * HD];
__device__ __align__(16) float g_vi [(size_t)NA * 3 * HD];
__device__ __align__(16) float g_v  [(size_t)NA * 3 * HD];
__device__ __align__(16) float g_osb[(size_t)NA * FHD];
__device__ __align__(16) float g_ovb[(size_t)NA * 3 * FHD];
__device__ __align__(16) float g_o  [(size_t)NA * FFK];
__device__ __align__(16) float g_h  [NM * FHD];
__device__ int g_molstart[NM + 1];

// ---------------- bf16 split-pack helper ----------------
__device__ __forceinline__ uint2 splitpack(float x0, float x1) {
    unsigned h;
    asm("cvt.rn.bf16x2.f32 %0, %1, %2;" : "=r"(h) : "f"(x1), "f"(x0));
    float h0 = __uint_as_float(h << 16);
    float h1 = __uint_as_float(h & 0xFFFF0000u);
    unsigned l;
    asm("cvt.rn.bf16x2.f32 %0, %1, %2;" : "=r"(l) : "f"(x1 - h1), "f"(x0 - h0));
    return make_uint2(h, l);
}

__device__ __forceinline__ uint4 splitpack4(float4 a) {
    uint2 r0 = splitpack(a.x, a.y);
    uint2 r1 = splitpack(a.z, a.w);
    return make_uint4(r0.x, r0.y, r1.x, r1.y);
}

// L1-bypass async copy (tiles have no L1 reuse; keep L1 for fp32 streams)
__device__ __forceinline__ void cp16(void* dst_smem, const void* src, int bytes) {
    unsigned sa = (unsigned)__cvta_generic_to_shared(dst_smem);
    asm volatile("cp.async.cg.shared.global [%0], [%1], 16, %2;\n"
                 :: "r"(sa), "l"(src), "r"(bytes));
}

#define MMA_BF16(ACC, AF, BF)                                                   \
    asm volatile(                                                               \
        "mma.sync.aligned.m16n8k16.row.col.f32.bf16.bf16.f32 "                  \
        "{%0,%1,%2,%3}, {%4,%5,%6,%7}, {%8,%9}, {%0,%1,%2,%3};\n"               \
        : "+f"(ACC[0]), "+f"(ACC[1]), "+f"(ACC[2]), "+f"(ACC[3])                \
        : "r"(AF[0]), "r"(AF[1]), "r"(AF[2]), "r"(AF[3]),                       \
          "r"(BF[0]), "r"(BF[1]))

// ---------------- bf16x3 dual-problem GEMM, 128x128 tile ----------------
#define ASTP 18
#define BSTP 132
#define STG_A (128 * ASTP)            // uint2
#define STG_B (16 * BSTP)             // uint2
#define STG_U2 (STG_A + STG_B)        // 4416 uint2 = 35328 B
#define SMEM_GEMM (2 * STG_U2 * 8)    // 70656 B

template<bool RELU, bool HAS_ADD, bool HAS_BIAS, bool WRITE_RAW>
__global__ __launch_bounds__(256, 2)
void bgemm_kernel(const uint2* __restrict__ A0, const uint2* __restrict__ B0,
                  const float* __restrict__ Add0, const float* __restrict__ bias0,
                  float* __restrict__ C0, float* __restrict__ Craw0,
                  int M0, int T0, int ldp0,
                  const uint2* __restrict__ A1, const uint2* __restrict__ B1,
                  const float* __restrict__ Add1, const float* __restrict__ bias1,
                  float* __restrict__ C1, float* __restrict__ Craw1,
                  int M1, int T1, int ldp1,
                  int N, int tiles0)
{
    extern __shared__ __align__(16) uint2 smem_u2[];

    const bool p1 = (int)blockIdx.y >= tiles0;
    const uint2* __restrict__ A   = p1 ? A1   : A0;
    const uint2* __restrict__ B   = p1 ? B1   : B0;
    const float* __restrict__ Add = p1 ? Add1 : Add0;
    const float* __restrict__ bias= p1 ? bias1: bias0;
    float* __restrict__ C    = p1 ? C1    : C0;
    float* __restrict__ Craw = p1 ? Craw1 : Craw0;
    const int M   = p1 ? M1   : M0;
    const int T   = p1 ? T1   : T0;
    const int ldp = p1 ? ldp1 : ldp0;
    const int rowBase = (p1 ? ((int)blockIdx.y - tiles0) : (int)blockIdx.y) * 128;

    const int tid = threadIdx.x;
    const int colBase = blockIdx.x * 128;
    const int warpId = tid >> 5;
    const int lane = tid & 31;
    const int g  = lane >> 2;
    const int tg = lane & 3;
    const int wm = (warpId & 1) * 64;
    const int wn = (warpId >> 1) * 32;

    float acc[4][4][4];
    #pragma unroll
    for (int mi = 0; mi < 4; mi++)
        #pragma unroll
        for (int ni = 0; ni < 4; ni++)
            #pragma unroll
            for (int j = 0; j < 4; j++) acc[mi][ni][j] = 0.f;

    auto load_stage = [&](int t, int st) {
        uint2* As = smem_u2 + st * STG_U2;
        uint2* Bs = As + STG_A;
        #pragma unroll
        for (int i = 0; i < 4; i++) {
            int c = tid + i * 256;
            int m = c >> 3, q = c & 7;
            int gm = rowBase + m;
            bool ok = gm < M;
            const uint2* src = ok ? (A + (size_t)gm * ldp + t * 16 + q * 2) : A;
            cp16(&As[m * ASTP + q * 2], src, ok ? 16 : 0);
        }
        #pragma unroll
        for (int i = 0; i < 4; i++) {
            int c = tid + i * 256;
            int j = c >> 6, q = c & 63;
            int gn = colBase + q * 2;
            bool ok = gn < N;
            const uint2* src = ok ? (B + (size_t)(t * 16 + j) * N + gn) : B;
            cp16(&Bs[j * BSTP + q * 2], src, ok ? 16 : 0);
        }
        asm volatile("cp.async.commit_group;\n");
    };

    load_stage(0, 0);

    for (int t = 0; t < T; t++) {
        const int st = t & 1;
        asm volatile("cp.async.wait_group 0;\n");
        __syncthreads();

        if (t + 1 < T) load_stage(t + 1, st ^ 1);

        const uint2* As = smem_u2 + st * STG_U2;
        const uint2* Bs = As + STG_A;

        #pragma unroll
        for (int ks = 0; ks < 2; ks++) {
            const int kb = ks * 8;
            unsigned ah[4][4], al[4][4], bh[4][2], bl[4][2];
            #pragma unroll
            for (int mi = 0; mi < 4; mi++) {
                int r = wm + mi * 16 + g;
                uint2 p0 = As[r * ASTP + kb + tg];
                uint2 q1 = As[(r + 8) * ASTP + kb + tg];
                uint2 p2 = As[r * ASTP + kb + 4 + tg];
                uint2 p3 = As[(r + 8) * ASTP + kb + 4 + tg];
                ah[mi][0] = p0.x; ah[mi][1] = q1.x; ah[mi][2] = p2.x; ah[mi][3] = p3.x;
                al[mi][0] = p0.y; al[mi][1] = q1.y; al[mi][2] = p2.y; al[mi][3] = p3.y;
            }
            #pragma unroll
            for (int ni = 0; ni < 4; ni++) {
                int n = wn + ni * 8 + g;
                uint2 q0 = Bs[(kb + tg) * BSTP + n];
                uint2 q1 = Bs[(kb + 4 + tg) * BSTP + n];
                bh[ni][0] = q0.x; bh[ni][1] = q1.x;
                bl[ni][0] = q0.y; bl[ni][1] = q1.y;
            }
            #pragma unroll
            for (int mi = 0; mi < 4; mi++)
                #pragma unroll
                for (int ni = 0; ni < 4; ni++) {
                    MMA_BF16(acc[mi][ni], ah[mi], bl[ni]);   // hi*lo
                    MMA_BF16(acc[mi][ni], al[mi], bh[ni]);   // lo*hi
                    MMA_BF16(acc[mi][ni], ah[mi], bh[ni]);   // hi*hi last
                }
        }
    }

    #pragma unroll
    for (int mi = 0; mi < 4; mi++) {
        int r0 = rowBase + wm + mi * 16 + g;
        #pragma unroll
        for (int ni = 0; ni < 4; ni++) {
            int cN = colBase + wn + ni * 8 + tg * 2;
            if (cN >= N) continue;
            #pragma unroll
            for (int half = 0; half < 2; half++) {
                int r = r0 + half * 8;
                if (r >= M) continue;
                size_t idx = (size_t)r * N + cN;
                float2 vv;
                vv.x = acc[mi][ni][half * 2 + 0];
                vv.y = acc[mi][ni][half * 2 + 1];
                if (HAS_ADD) {
                    float2 a = *(const float2*)(Add + idx);
                    vv.x += a.x; vv.y += a.y;
                }
                if (HAS_BIAS) {
                    float2 b = *(const float2*)(bias + cN);
                    vv.x += b.x; vv.y += b.y;
                }
                if (WRITE_RAW) *(float2*)(Craw + idx) = vv;
                if (RELU) { vv.x = fmaxf(vv.x, 0.f); vv.y = fmaxf(vv.y, 0.f); }
                *(float2*)(C + idx) = vv;
            }
        }
    }
}

// ---------------- batched weight split-pack: all 7 weights in one launch ----------------
struct PackJob {
    const float* W; uint2* out;
    int N, JP, s0, l0, d0, s1, l1, d1;
};
struct PackJobs { PackJob j[7]; };

__global__ void packAll_kernel(PackJobs jobs)
{
    PackJob jb = jobs.j[blockIdx.y];
    long tot = (long)jb.JP * jb.N;
    for (long idx = (long)blockIdx.x * blockDim.x + threadIdx.x; idx < tot;
         idx += (long)gridDim.x * blockDim.x) {
        int j = (int)(idx / jb.N), n = (int)(idx % jb.N);
        float v[2];
        #pragma unroll
        for (int e = 0; e < 2; e++) {
            int k = 2 * j + e, row = -1;
            if (k >= jb.d1 && k < jb.d1 + jb.l1) row = jb.s1 + (k - jb.d1);
            else if (k >= jb.d0 && k < jb.d0 + jb.l0) row = jb.s0 + (k - jb.d0);
            v[e] = (row < 0) ? 0.f : jb.W[(size_t)row * jb.N + n];
        }
        jb.out[idx] = splitpack(v[0], v[1]);
    }
}

// ---------------- f_atoms -> packed ----------------
__global__ void pack_fa_kernel(const float* __restrict__ fa, uint2* __restrict__ out)
{
    long tot = (long)NA * JP_FA;
    for (long idx = (long)blockIdx.x * blockDim.x + threadIdx.x; idx < tot;
         idx += (long)gridDim.x * blockDim.x) {
        int n = (int)(idx / JP_FA), j = (int)(idx % JP_FA);
        int k0 = 2 * j;
        float v0 = (k0     < FD) ? fa[(size_t)n * FD + k0]     : 0.f;
        float v1 = (k0 + 1 < FD) ? fa[(size_t)n * FD + k0 + 1] : 0.f;
        out[idx] = splitpack(v0, v1);
    }
}

// ---------------- build X packed: rows (n*3+c), K layout [a(134)|self(134)] ----------------
__global__ void build_X_kernel(const float* __restrict__ f_atoms, const float* __restrict__ f_bonds,
                               const int* __restrict__ a2a, const int* __restrict__ a2b,
                               uint2* __restrict__ Xp)
{
    int n = blockIdx.x;
    __shared__ int   nb[KNB];
    __shared__ float bond[KNB][3];
    __shared__ float stg[6][134];
    if (threadIdx.x < KNB) {
        int k = threadIdx.x;
        nb[k] = a2a[n * KNB + k];
        int b = a2b[n * KNB + k];
        bond[k][0] = f_bonds[(size_t)b * 3 + 0];
        bond[k][1] = f_bonds[(size_t)b * 3 + 1];
        bond[k][2] = f_bonds[(size_t)b * 3 + 2];
    }
    if (threadIdx.x < 6) stg[threadIdx.x][133] = 0.f;
    __syncthreads();
    float ms0 = 0.f, ms1 = 0.f, ms2 = 0.f;
    #pragma unroll
    for (int k = 0; k < KNB; k++) {
        float mk = (nb[k] > 0) ? 1.f : 0.f;
        ms0 += mk * bond[k][0];
        ms1 += mk * bond[k][1];
        ms2 += mk * bond[k][2];
    }
    for (int f = threadIdx.x; f < FD; f += blockDim.x) {
        float selfv = f_atoms[(size_t)n * FD + f];
        float a0 = 0.f, a1 = 0.f, a2 = 0.f;
        #pragma unroll
        for (int k = 0; k < KNB; k++) {
            float fv = f_atoms[(size_t)nb[k] * FD + f];
            a0 += fv * bond[k][0];
            a1 += fv * bond[k][1];
            a2 += fv * bond[k][2];
        }
        stg[0][f] = a0; stg[1][f] = a1; stg[2][f] = a2;
        stg[3][f] = selfv * ms0; stg[4][f] = selfv * ms1; stg[5][f] = selfv * ms2;
    }
    __syncthreads();
    for (int t = threadIdx.x; t < 3 * JP_X; t += blockDim.x) {
        int c = t / JP_X, j = t % JP_X;
        float v[2];
        #pragma unroll
        for (int e = 0; e < 2; e++) {
            int k = 2 * j + e;
            if (k < 134)      v[e] = stg[c][k];
            else if (k < 268) v[e] = stg[3 + c][k - 134];
            else              v[e] = 0.f;
        }
        Xp[((size_t)n * 3 + c) * JP_X + j] = splitpack(v[0], v[1]);
    }
}

// ---------------- message-passing gather -> packed (float4 loads; invnorm fused) ----------------
__global__ void gather_kernel(const float* __restrict__ s, const float* __restrict__ v,
                              const int* __restrict__ a2a,
                              uint2* __restrict__ sagg_p, uint2* __restrict__ vagg_p)
{
    int n = blockIdx.x;
    __shared__ int nb[KNB];
    if (threadIdx.x < KNB) nb[threadIdx.x] = a2a[n * KNB + threadIdx.x];
    __syncthreads();
    int cnt = 0;
    #pragma unroll
    for (int k = 0; k < KNB; k++) cnt += (nb[k] > 0) ? 1 : 0;
    const float sc = 1.f / (float)max(cnt, 1);

    const float4* s4 = (const float4*)s;
    const float4* v4 = (const float4*)v;
    size_t b0 = (size_t)nb[0] * 275, b1 = (size_t)nb[1] * 275, b2 = (size_t)nb[2] * 275;
    size_t b3 = (size_t)nb[3] * 275, b4 = (size_t)nb[4] * 275, b5 = (size_t)nb[5] * 275;

    uint2* sd = sagg_p + (size_t)n * JP_H;
    for (int t = threadIdx.x; t < 280; t += blockDim.x) {
        if (t < 275) {
            float4 x0 = s4[b0+t], x1 = s4[b1+t], x2 = s4[b2+t];
            float4 x3 = s4[b3+t], x4 = s4[b4+t], x5 = s4[b5+t];
            float4 a;
            a.x = x0.x + x1.x + x2.x + x3.x + x4.x + x5.x;
            a.y = x0.y + x1.y + x2.y + x3.y + x4.y + x5.y;
            a.z = x0.z + x1.z + x2.z + x3.z + x4.z + x5.z;
            a.w = x0.w + x1.w + x2.w + x3.w + x4.w + x5.w;
            *(uint4*)(sd + 2 * t) = splitpack4(a);
        } else {
            *(uint4*)(sd + 550 + 2 * (t - 275)) = make_uint4(0, 0, 0, 0);
        }
    }
    size_t c0 = b0 * 3, c1 = b1 * 3, c2 = b2 * 3, c3 = b3 * 3, c4 = b4 * 3, c5 = b5 * 3;
    for (int t = threadIdx.x; t < 840; t += blockDim.x) {
        int c = t / 280, u = t % 280;
        uint2* dst = vagg_p + ((size_t)n * 3 + c) * JP_H;
        if (u < 275) {
            size_t e = (size_t)c * 275 + u;
            float4 x0 = v4[c0+e], x1 = v4[c1+e], x2 = v4[c2+e];
            float4 x3 = v4[c3+e], x4 = v4[c4+e], x5 = v4[c5+e];
            float4 a;
            a.x = (x0.x + x1.x + x2.x + x3.x + x4.x + x5.x) * sc;
            a.y = (x0.y + x1.y + x2.y + x3.y + x4.y + x5.y) * sc;
            a.z = (x0.z + x1.z + x2.z + x3.z + x4.z + x5.z) * sc;
            a.w = (x0.w + x1.w + x2.w + x3.w + x4.w + x5.w) * sc;
            *(uint4*)(dst + 2 * u) = splitpack4(a);
        } else {
            *(uint4*)(dst + 550 + 2 * (u - 275)) = make_uint4(0, 0, 0, 0);
        }
    }
}

// ---------------- output-stage concat builders (gather fused, float4) ----------------
__global__ void build_osin_kernel(const float* __restrict__ fa, const float* __restrict__ s,
                                  const int* __restrict__ a2a, uint2* __restrict__ osin_p)
{
    int n = blockIdx.x;
    __shared__ int nb[KNB];
    if (threadIdx.x < KNB) nb[threadIdx.x] = a2a[n * KNB + threadIdx.x];
    __syncthreads();
    const float4* s4 = (const float4*)s;
    size_t b0 = (size_t)nb[0] * 275, b1 = (size_t)nb[1] * 275, b2 = (size_t)nb[2] * 275;
    size_t b3 = (size_t)nb[3] * 275, b4 = (size_t)nb[4] * 275, b5 = (size_t)nb[5] * 275;
    uint2* dst = osin_p + (size_t)n * JP_OS;
    for (int t = threadIdx.x; t < 67 + 275 + 7; t += blockDim.x) {
        if (t < 67) {
            int k0 = 2 * t;
            float v0 = fa[(size_t)n * FD + k0];
            float v1 = (k0 + 1 < FD) ? fa[(size_t)n * FD + k0 + 1] : 0.f;
            dst[t] = splitpack(v0, v1);
        } else if (t < 342) {
            int w = t - 67;
            float4 x0 = s4[b0+w], x1 = s4[b1+w], x2 = s4[b2+w];
            float4 x3 = s4[b3+w], x4 = s4[b4+w], x5 = s4[b5+w];
            float4 a;
            a.x = x0.x + x1.x + x2.x + x3.x + x4.x + x5.x;
            a.y = x0.y + x1.y + x2.y + x3.y + x4.y + x5.y;
            a.z = x0.z + x1.z + x2.z + x3.z + x4.z + x5.z;
            a.w = x0.w + x1.w + x2.w + x3.w + x4.w + x5.w;
            dst[67 + 2 * w] = splitpack(a.x, a.y);
            dst[68 + 2 * w] = splitpack(a.z, a.w);
        } else {
            dst[617 + (t - 342)] = make_uint2(0, 0);
        }
    }
}

__global__ void build_ovin_kernel(const float* __restrict__ vi, const float* __restrict__ v,
                                  const int* __restrict__ a2a, uint2* __restrict__ ovin_p)
{
    int n = blockIdx.x;
    __shared__ int nb[KNB];
    if (threadIdx.x < KNB) nb[threadIdx.x] = a2a[n * KNB + threadIdx.x];
    __syncthreads();
    const float4* vi4 = (const float4*)vi;
    const float4* v4  = (const float4*)v;
    size_t c0 = (size_t)nb[0] * 825, c1 = (size_t)nb[1] * 825, c2 = (size_t)nb[2] * 825;
    size_t c3 = (size_t)nb[3] * 825, c4 = (size_t)nb[4] * 825, c5 = (size_t)nb[5] * 825;
    for (int t = threadIdx.x; t < 3 * 552; t += blockDim.x) {
        int c = t / 552, u = t % 552;
        uint2* dst = ovin_p + ((size_t)n * 3 + c) * JP_OV;
        if (u < 275) {
            float4 x = vi4[((size_t)n * 3 + c) * 275 + u];
            *(uint4*)(dst + 2 * u) = splitpack4(x);
        } else if (u < 550) {
            int w = u - 275;
            size_t e = (size_t)c * 275 + w;
            float4 x0 = v4[c0+e], x1 = v4[c1+e], x2 = v4[c2+e];
            float4 x3 = v4[c3+e], x4 = v4[c4+e], x5 = v4[c5+e];
            float4 a;
            a.x = x0.x + x1.x + x2.x + x3.x + x4.x + x5.x;
            a.y = x0.y + x1.y + x2.y + x3.y + x4.y + x5.y;
            a.z = x0.z + x1.z + x2.z + x3.z + x4.z + x5.z;
            a.w = x0.w + x1.w + x2.w + x3.w + x4.w + x5.w;
            *(uint4*)(dst + 550 + 2 * w) = splitpack4(a);
        } else {
            *(uint4*)(dst + 1100 + 2 * (u - 550)) = make_uint4(0, 0, 0, 0);
        }
    }
}

// o[n] = [osb | sum_c ovb], float4
__global__ void build_o_kernel(const float* __restrict__ osb, const float* __restrict__ ovb,
                               float* __restrict__ o)
{
    const float4* osb4 = (const float4*)osb;   // row 175
    const float4* ovb4 = (const float4*)ovb;   // row 525
    float4* o4 = (float4*)o;                   // row 350
    long tot = (long)NA * 350;
    for (long idx = (long)blockIdx.x * blockDim.x + threadIdx.x; idx < tot;
         idx += (long)gridDim.x * blockDim.x) {
        int n = (int)(idx / 350);
        int j = (int)(idx % 350);
        float4 r;
        if (j < 175) {
            r = osb4[(size_t)n * 175 + j];
        } else {
            size_t b = (size_t)n * 525 + (j - 175);
            float4 x0 = ovb4[b], x1 = ovb4[b + 175], x2 = ovb4[b + 350];
            r.x = x0.x + x1.x + x2.x;
            r.y = x0.y + x1.y + x2.y;
            r.z = x0.z + x1.z + x2.z;
            r.w = x0.w + x1.w + x2.w;
        }
        o4[idx] = r;
    }
}

// ---------------- readout ----------------
__global__ void mol_start_kernel(const int* __restrict__ ids, int* __restrict__ start)
{
    int m = blockIdx.x * blockDim.x + threadIdx.x;
    if (m > NM) return;
    int lo = 0, hi = NA;
    while (lo < hi) {
        int mid = (lo + hi) >> 1;
        if (ids[mid] < m) lo = mid + 1; else hi = mid;
    }
    start[m] = lo;
}

__global__ void segment_mean_kernel(const float* __restrict__ o, const int* __restrict__ start,
                                    uint2* __restrict__ mol_p)
{
    int m = blockIdx.x;
    int s0 = start[m], e0 = start[m + 1];
    int cnt = e0 - s0;
    if (s0 == 0 && e0 > 0) cnt -= 1;   // atom 0 is padding
    float sc = 1.f / (float)max(cnt, 1);
    const float4* o4 = (const float4*)o;
    uint2* dst = mol_p + (size_t)m * JP_FF;
    for (int t = threadIdx.x; t < 352; t += blockDim.x) {
        if (t < 350) {
            float4 a = make_float4(0.f, 0.f, 0.f, 0.f);
            for (int n = s0; n < e0; n++) {
                if (n == 0) continue;
                float4 x = o4[(size_t)n * 350 + t];
                a.x += x.x; a.y += x.y; a.z += x.z; a.w += x.w;
            }
            a.x *= sc; a.y *= sc; a.z *= sc; a.w *= sc;
            *(uint4*)(dst + 2 * t) = splitpack4(a);
        } else {
            *(uint4*)(dst + 700 + 2 * (t - 350)) = make_uint4(0, 0, 0, 0);
        }
    }
}

__global__ void ffn_out_kernel(const float* __restrict__ h, const float* __restrict__ W2,
                               const float* __restrict__ b2, float* __restrict__ out)
{
    int m = blockIdx.x;
    float acc = 0.f;
    for (int j = threadIdx.x; j < FHD; j += 256) acc += h[m * FHD + j] * W2[j];
    __shared__ float red[256];
    red[threadIdx.x] = acc;
    __syncthreads();
    for (int st = 128; st > 0; st >>= 1) {
        if (threadIdx.x < st) red[threadIdx.x] += red[threadIdx.x + st];
        __syncthreads();
    }
    if (threadIdx.x == 0) out[m] = red[0] + b2[0];
}

// ---------------- launch ----------------
extern "C" void kernel_launch(void* const* d_in, const int* in_sizes, int n_in,
                              void* d_out, int out_size)
{
    const float* f_atoms = (const float*)d_in[0];
    const float* f_bonds = (const float*)d_in[1];
    const float* W_is    = (const float*)d_in[2];
    const float* W_iv    = (const float*)d_in[3];
    const float* W_hs    = (const float*)d_in[4];
    const float* W_hv    = (const float*)d_in[5];
    const float* W_os    = (const float*)d_in[6];
    const float* b_os    = (const float*)d_in[7];
    const float* W_ov    = (const float*)d_in[8];
    const float* b_ov    = (const float*)d_in[9];
    const float* ffn_W1  = (const float*)d_in[10];
    const float* ffn_b1  = (const float*)d_in[11];
    const float* ffn_W2  = (const float*)d_in[12];
    const float* ffn_b2  = (const float*)d_in[13];
    const int*   a2a     = (const int*)d_in[14];
    const int*   a2b     = (const int*)d_in[15];
    const int*   mol_ids = (const int*)d_in[16];
    float*       out     = (float*)d_out;

    uint2 *p_fa, *p_X, *p_sagg, *p_vagg, *p_osin, *p_ovin, *p_mol;
    uint2 *p_Wis, *p_Wiv, *p_Whs, *p_Whv, *p_Wos, *p_Wov, *p_Wff;
    float *p_si, *p_s, *p_vi, *p_v, *p_osb, *p_ovb, *p_o, *p_h;
    int* p_molstart;
    cudaGetSymbolAddress((void**)&p_fa,   g_fa_p);
    cudaGetSymbolAddress((void**)&p_X,    g_X_p);
    cudaGetSymbolAddress((void**)&p_sagg, g_sagg_p);
    cudaGetSymbolAddress((void**)&p_vagg, g_vagg_p);
    cudaGetSymbolAddress((void**)&p_osin, g_osin_p);
    cudaGetSymbolAddress((void**)&p_ovin, g_ovin_p);
    cudaGetSymbolAddress((void**)&p_mol,  g_mol_p);
    cudaGetSymbolAddress((void**)&p_Wis,  g_Wis_p);
    cudaGetSymbolAddress((void**)&p_Wiv,  g_Wiv_p);
    cudaGetSymbolAddress((void**)&p_Whs,  g_Whs_p);
    cudaGetSymbolAddress((void**)&p_Whv,  g_Whv_p);
    cudaGetSymbolAddress((void**)&p_Wos,  g_Wos_p);
    cudaGetSymbolAddress((void**)&p_Wov,  g_Wov_p);
    cudaGetSymbolAddress((void**)&p_Wff,  g_Wff_p);
    cudaGetSymbolAddress((void**)&p_si,   g_si);
    cudaGetSymbolAddress((void**)&p_s,    g_s);
    cudaGetSymbolAddress((void**)&p_vi,   g_vi);
    cudaGetSymbolAddress((void**)&p_v,    g_v);
    cudaGetSymbolAddress((void**)&p_osb,  g_osb);
    cudaGetSymbolAddress((void**)&p_ovb,  g_ovb);
    cudaGetSymbolAddress((void**)&p_o,    g_o);
    cudaGetSymbolAddress((void**)&p_h,    g_h);
    cudaGetSymbolAddress((void**)&p_molstart, g_molstart);

    cudaFuncSetAttribute(bgemm_kernel<true,false,false,true>,
                         cudaFuncAttributeMaxDynamicSharedMemorySize, SMEM_GEMM);
    cudaFuncSetAttribute(bgemm_kernel<true,true,false,false>,
                         cudaFuncAttributeMaxDynamicSharedMemorySize, SMEM_GEMM);
    cudaFuncSetAttribute(bgemm_kernel<true,false,true,false>,
                         cudaFuncAttributeMaxDynamicSharedMemorySize, SMEM_GEMM);

    const int tilesS = (NA + 127) / 128;          // 157
    const int tilesV = (3 * NA + 127) / 128;      // 469
    const int tilesM = (NM + 127) / 128;          // 7

    // 0: all weight packs in one launch
    {
        PackJobs jobs;
        jobs.j[0] = { W_is,   p_Wis, HD,  JP_FA, 0, 133,  0, 0,    0,   0   };
        jobs.j[1] = { W_iv,   p_Wiv, HD,  JP_X,  0, 133,  0, 133,  133, 134 };
        jobs.j[2] = { W_hs,   p_Whs, HD,  JP_H,  0, 1100, 0, 0,    0,   0   };
        jobs.j[3] = { W_hv,   p_Whv, HD,  JP_H,  0, 1100, 0, 0,    0,   0   };
        jobs.j[4] = { W_os,   p_Wos, FHD, JP_OS, 0, 133,  0, 133,  1100,134 };
        jobs.j[5] = { W_ov,   p_Wov, FHD, JP_OV, 0, 2200, 0, 0,    0,   0   };
        jobs.j[6] = { ffn_W1, p_Wff, FHD, JP_FF, 0, 1400, 0, 0,    0,   0   };
        dim3 g(256, 7);
        packAll_kernel<<<g, 256>>>(jobs);
    }

    // 1, 2: activation prep
    pack_fa_kernel<<<2048, 256>>>(f_atoms, p_fa);
    build_X_kernel<<<NA, 192>>>(f_atoms, f_bonds, a2a, a2b, p_X);

    // 3: si & vi fused GEMM  (my index 3 == ncu launch index 5 -> profiled)
    {
        dim3 g((HD + 127) / 128, tilesS + tilesV);
        bgemm_kernel<true, false, false, true><<<g, 256, SMEM_GEMM>>>(
            p_fa, p_Wis, nullptr, nullptr, p_s, p_si, NA, 5, JP_FA,
            p_X,  p_Wiv, nullptr, nullptr, p_v, p_vi, 3 * NA, 9, JP_X,
            HD, tilesS);
    }

    // message passing: s & v GEMMs fused per iteration
    for (int it = 0; it < 6; it++) {
        gather_kernel<<<NA, 256>>>(p_s, p_v, a2a, p_sagg, p_vagg);
        dim3 g((HD + 127) / 128, tilesS + tilesV);
        bgemm_kernel<true, true, false, false><<<g, 256, SMEM_GEMM>>>(
            p_sagg, p_Whs, p_si, nullptr, p_s, nullptr, NA, 35, JP_H,
            p_vagg, p_Whv, p_vi, nullptr, p_v, nullptr, 3 * NA, 35, JP_H,
            HD, tilesS);
    }

    // output stage: os & ov GEMMs fused
    build_osin_kernel<<<NA, 256>>>(f_atoms, p_s, a2a, p_osin);
    build_ovin_kernel<<<NA, 256>>>(p_vi, p_v, a2a, p_ovin);
    {
        dim3 g((FHD + 127) / 128, tilesS + tilesV);
        bgemm_kernel<true, false, true, false><<<g, 256, SMEM_GEMM>>>(
            p_osin, p_Wos, nullptr, b_os, p_osb, nullptr, NA, 39, JP_OS,
            p_ovin, p_Wov, nullptr, b_ov, p_ovb, nullptr, 3 * NA, 69, JP_OV,
            FHD, tilesS);
    }
    {
        long tot3 = (long)NA * 350;
        build_o_kernel<<<(unsigned)((tot3 + 255) / 256), 256>>>(p_osb, p_ovb, p_o);
    }

    // readout + FFN
    mol_start_kernel<<<4, 256>>>(mol_ids, p_molstart);
    segment_mean_kernel<<<NM, 256>>>(p_o, p_molstart, p_mol);
    {
        dim3 g((FHD + 127) / 128, tilesM);
        bgemm_kernel<true, false, true, false><<<g, 256, SMEM_GEMM>>>(
            p_mol, p_Wff, nullptr, ffn_b1, p_h, nullptr, NM, 44, JP_FF,
            p_mol, p_Wff, nullptr, ffn_b1, p_h, nullptr, NM, 44, JP_FF,
            FHD, tilesM);
    }
    ffn_out_kernel<<<NM, 256>>>(p_h, ffn_W2, ffn_b2, out);
}